// round 10
// baseline (speedup 1.0000x reference)
#include <cuda_runtime.h>
#include <cuda_fp16.h>
#include <math.h>
#include <stdint.h>

// ---------------------------------------------------------------------------
// Problem constants
// ---------------------------------------------------------------------------
#define NB   32
#define NL   4096
#define NH   512
#define NC   1025
#define MTOT (NB * NL)   // 131072

#define MT   128         // m rows per CTA
#define NST  16          // 4 h-tiles x 4 k-stages of 128

// SMEM layout
#define A_ROWB 1040                    // 512 fp16 + 16B pad
#define SM_A   0
#define A_BYTES (128 * A_ROWB)         // 133120
#define B_ROWB 272                     // 128 fp16 + 16B pad
#define B_TILE (128 * B_ROWB)          // 34816
#define SM_B   A_BYTES
#define SM_TAB (A_BYTES + 2 * B_TILE)  // 202752
// tables: w2[512] base[512] wcov[512] red[512] lac[128]
#define SMEM_TOTAL (SM_TAB + 8704)     // 211456

// ---------------------------------------------------------------------------
// Device scratch (static; no runtime allocation)
// ---------------------------------------------------------------------------
__device__ float g_base[NB * NH];
__device__ float g_logits[MTOT];
__device__ __half g_Bf[NH * 512];             // W1[:,0:512] fp16
__device__ float g_ctx_part[32 * NB * 512];

// ---------------------------------------------------------------------------
// helpers
// ---------------------------------------------------------------------------
__device__ __forceinline__ uint32_t smem_u32(const void* p) {
    uint32_t a;
    asm("{ .reg .u64 t; cvta.to.shared.u64 t, %1; cvt.u32.u64 %0, t; }"
        : "=r"(a) : "l"(p));
    return a;
}

__device__ __forceinline__ void ldsm4(uint32_t addr, uint32_t& r0, uint32_t& r1,
                                      uint32_t& r2, uint32_t& r3) {
    asm volatile("ldmatrix.sync.aligned.m8n8.x4.shared.b16 {%0,%1,%2,%3}, [%4];"
                 : "=r"(r0), "=r"(r1), "=r"(r2), "=r"(r3) : "r"(addr));
}

__device__ __forceinline__ void mma16816(float* d, uint32_t a0, uint32_t a1,
                                         uint32_t a2, uint32_t a3, uint32_t b0,
                                         uint32_t b1) {
    asm volatile(
        "mma.sync.aligned.m16n8k16.row.col.f32.f16.f16.f32 "
        "{%0,%1,%2,%3}, {%4,%5,%6,%7}, {%8,%9}, {%0,%1,%2,%3};"
        : "+f"(d[0]), "+f"(d[1]), "+f"(d[2]), "+f"(d[3])
        : "r"(a0), "r"(a1), "r"(a2), "r"(a3), "r"(b0), "r"(b1));
}

__device__ __forceinline__ void cpasync16(uint32_t dst, const void* src) {
    asm volatile("cp.async.cg.shared.global [%0], [%1], 16;"
                 :: "r"(dst), "l"(src) : "memory");
}
#define CP_COMMIT() asm volatile("cp.async.commit_group;" ::: "memory")
#define CP_WAIT0()  asm volatile("cp.async.wait_group 0;" ::: "memory")

__device__ __forceinline__ float fast_tanh(float x) {
    float t = x * 2.885390081777927f;  // 2*log2(e)
    float e;
    asm("ex2.approx.f32 %0, %1;" : "=f"(e) : "f"(t));
    float r;
    asm("rcp.approx.f32 %0, %1;" : "=f"(r) : "f"(e + 1.0f));
    return 1.0f - 2.0f * r;
}
__device__ __forceinline__ float fast_exp(float x) {
    float t = x * 1.4426950408889634f;
    float e;
    asm("ex2.approx.f32 %0, %1;" : "=f"(e) : "f"(t));
    return e;
}
__device__ __forceinline__ uint32_t pack_h2(__half a, __half b) {
    __half2 v = __halves2half2(a, b);
    return *reinterpret_cast<uint32_t*>(&v);
}

// ---------------------------------------------------------------------------
// K-1b: W1[:,0:512] -> fp16
// ---------------------------------------------------------------------------
__global__ void convB_kernel(const float* __restrict__ W1) {
    int h = blockIdx.x;
    int k = threadIdx.x;
    g_Bf[h * 512 + k] = __float2half_rn(W1[(size_t)h * NC + k]);
}

// ---------------------------------------------------------------------------
// K0: base[b,h] = b1[h] + sum_c summary[b,c]*W1[h,512+c]  (exact fp32)
// ---------------------------------------------------------------------------
__global__ void base_kernel(const float* __restrict__ summary,
                            const float* __restrict__ W1,
                            const float* __restrict__ b1) {
    int b = blockIdx.x;
    int h = threadIdx.x;
    __shared__ float ss[512];
    ss[h] = summary[b * 512 + h];
    __syncthreads();
    const float* w = W1 + (size_t)h * NC + 512;
    float acc = b1[h];
#pragma unroll 8
    for (int c = 0; c < 512; c++) acc += ss[c] * w[c];
    g_base[b * NH + h] = acc;
}

// ---------------------------------------------------------------------------
// K1: HMMA GEMM. 256 threads = 8 warps (2m x 4n), each warp 64m x 32n
// (cuts smem crossbar traffic to 192KB/stage vs 256KB for 4x4).
// A fp32->fp16 conversion pipelined through the first h-tile.
// Flat 16-stage B pipeline.
// ---------------------------------------------------------------------------
__global__ __launch_bounds__(256, 1) void gemm_kernel(
    const float* __restrict__ ts, const float* __restrict__ W1,
    const float* __restrict__ W2, const float* __restrict__ coverage,
    const int* __restrict__ tlen) {
    extern __shared__ char smem[];
    const uint32_t sb = smem_u32(smem);
    const int tid = threadIdx.x;
    const int lane = tid & 31;
    const int warp = tid >> 5;
    const int wm = warp & 1;   // m half (64 rows)
    const int wn = warp >> 1;  // n quarter (32 cols)

    const int bid = blockIdx.x;
    const int b = bid >> 5;
    const int l0 = (bid & 31) * 128;
    if (l0 >= tlen[b]) return;
    const size_t m0 = (size_t)bid * MT;

    float* s_w2 = (float*)(smem + SM_TAB);            // 512
    float* s_base = (float*)(smem + SM_TAB + 2048);   // 512
    float* s_wcov = (float*)(smem + SM_TAB + 4096);   // 512
    float* s_red = (float*)(smem + SM_TAB + 6144);    // 128 x 4
    float* s_lac = (float*)(smem + SM_TAB + 8192);    // 128

    if (tid < 128) s_lac[tid] = 0.0f;

    // ---- prologue: B stage 0 (async) + A chunk 0 conversion + tables ----
    {
        // B stage 0: 2048 16B chunks, 8 per thread
#pragma unroll
        for (int i = 0; i < 8; i++) {
            int e = tid + i * 256;
            int r = e >> 4, c = e & 15;
            cpasync16(sb + SM_B + (uint32_t)(r * B_ROWB + c * 16),
                      g_Bf + (size_t)r * 512 + c * 8);
        }
        CP_COMMIT();

        // A chunk 0: 4096 float4 slots (cols 0..127), 16 per thread
#pragma unroll
        for (int i = 0; i < 16; i++) {
            int e = tid + i * 256;
            int r = e >> 5, q = e & 31;
            float4 v = *(const float4*)(ts + (m0 + r) * 512 + q * 4);
            *(uint2*)(smem + r * A_ROWB + q * 8) = make_uint2(
                pack_h2(__float2half_rn(v.x), __float2half_rn(v.y)),
                pack_h2(__float2half_rn(v.z), __float2half_rn(v.w)));
        }

        // tables (512 entries each), 2 per thread
#pragma unroll
        for (int i = 0; i < 2; i++) {
            int h = tid + i * 256;
            s_w2[h] = W2[h];
            s_base[h] = g_base[b * NH + h];
            s_wcov[h] = W1[(size_t)h * NC + 1024];
        }
        CP_WAIT0();
        __syncthreads();
    }

    const uint32_t aBase =
        sb + (uint32_t)((wm * 64 + (lane & 15)) * A_ROWB + (lane >> 4) * 16);
    const uint32_t bBase0 =
        sb + SM_B +
        (uint32_t)((wn * 32 + (lane & 7) + ((lane >> 4) & 1) * 8) * B_ROWB +
                   ((lane >> 3) & 1) * 16);

    float acc[4][4][4];   // [tm 16-row][tn 8-col][frag]
#pragma unroll
    for (int i = 0; i < 4; i++)
#pragma unroll
        for (int j = 0; j < 4; j++)
#pragma unroll
            for (int c = 0; c < 4; c++) acc[i][j][c] = 0.0f;

    for (int g = 0; g < NST; g++) {
        const uint32_t bo = (uint32_t)((g & 1) * B_TILE);

        // issue next B stage into the other buffer (8 chunks/thread)
        if (g < NST - 1) {
            const int gn = g + 1;
            const int htn = gn >> 2, sn = gn & 3;
            const uint32_t nbo = (uint32_t)((gn & 1) * B_TILE);
#pragma unroll
            for (int i = 0; i < 8; i++) {
                int e = tid + i * 256;
                int r = e >> 4, c = e & 15;
                cpasync16(sb + SM_B + nbo + (uint32_t)(r * B_ROWB + c * 16),
                          g_Bf + (size_t)(htn * 128 + r) * 512 + sn * 128 +
                              c * 8);
            }
            CP_COMMIT();
        }

        // A prefetch (first h-tile only): chunk g+1 in 4 groups of 4 float4
        const bool aPre = (g < 3);
        float4 av[4];
        if (aPre) {
#pragma unroll
            for (int i = 0; i < 4; i++) {
                int e = tid + i * 256;
                int r = e >> 5, q = e & 31;
                av[i] = *(const float4*)(ts + (m0 + r) * 512 + (g + 1) * 128 +
                                         q * 4);
            }
        }

        const uint32_t aOff = (uint32_t)((g & 3) * 256);
#pragma unroll
        for (int ks = 0; ks < 8; ks++) {
            uint32_t a[4][4];
#pragma unroll
            for (int tm = 0; tm < 4; tm++)
                ldsm4(aBase + aOff + ks * 32 + tm * 16 * A_ROWB, a[tm][0],
                      a[tm][1], a[tm][2], a[tm][3]);
#pragma unroll
            for (int tp = 0; tp < 2; tp++) {
                uint32_t b0, b1, b2, b3;
                ldsm4(bBase0 + bo + ks * 32 + tp * 16 * B_ROWB, b0, b1, b2, b3);
#pragma unroll
                for (int tm = 0; tm < 4; tm++) {
                    mma16816(acc[tm][2 * tp], a[tm][0], a[tm][1], a[tm][2],
                             a[tm][3], b0, b1);
                    mma16816(acc[tm][2 * tp + 1], a[tm][0], a[tm][1], a[tm][2],
                             a[tm][3], b2, b3);
                }
            }

            // A-conversion hooks at odd k-steps
            if (aPre && (ks & 1)) {
                const int gi = ks >> 1;
#pragma unroll
                for (int i = 0; i < 4; i++) {
                    int e = tid + (gi * 4 + i) * 256;
                    int r = e >> 5, q = e & 31;
                    *(uint2*)(smem + r * A_ROWB + (g + 1) * 256 + q * 8) =
                        make_uint2(pack_h2(__float2half_rn(av[i].x),
                                           __float2half_rn(av[i].y)),
                                   pack_h2(__float2half_rn(av[i].z),
                                           __float2half_rn(av[i].w)));
                }
                if (gi < 3) {
#pragma unroll
                    for (int i = 0; i < 4; i++) {
                        int e = tid + ((gi + 1) * 4 + i) * 256;
                        int r = e >> 5, q = e & 31;
                        av[i] = *(const float4*)(ts + (m0 + r) * 512 +
                                                 (g + 1) * 128 + q * 4);
                    }
                }
            }
        }

        // h-tile boundary: fused epilogue, reset accumulators
        if ((g & 3) == 3) {
            const int h0 = (g >> 2) * 128;
#pragma unroll
            for (int tm = 0; tm < 4; tm++) {
#pragma unroll
                for (int rh = 0; rh < 2; rh++) {
                    int m_local = wm * 64 + tm * 16 + rh * 8 + (lane >> 2);
                    float cov = coverage[m0 + m_local];
                    float rs = 0.0f;
#pragma unroll
                    for (int tn = 0; tn < 4; tn++) {
                        int h = h0 + wn * 32 + tn * 8 + (lane & 3) * 2;
                        float p0 = acc[tm][tn][rh * 2 + 0] + s_base[h] +
                                   cov * s_wcov[h];
                        float p1 = acc[tm][tn][rh * 2 + 1] + s_base[h + 1] +
                                   cov * s_wcov[h + 1];
                        rs += fast_tanh(p0) * s_w2[h] +
                              fast_tanh(p1) * s_w2[h + 1];
                    }
                    rs += __shfl_xor_sync(0xffffffffu, rs, 1);
                    rs += __shfl_xor_sync(0xffffffffu, rs, 2);
                    if ((lane & 3) == 0) s_red[m_local * 4 + wn] = rs;
#pragma unroll
                    for (int tn = 0; tn < 4; tn++) {
                        acc[tm][tn][rh * 2 + 0] = 0.0f;
                        acc[tm][tn][rh * 2 + 1] = 0.0f;
                    }
                }
            }
            __syncthreads();
            if (tid < 128)
                s_lac[tid] += (s_red[tid * 4] + s_red[tid * 4 + 1]) +
                              (s_red[tid * 4 + 2] + s_red[tid * 4 + 3]);
        }

        if (g < NST - 1) CP_WAIT0();
        __syncthreads();
    }

    if (tid < 128) g_logits[m0 + tid] = s_lac[tid];
}

// ---------------------------------------------------------------------------
// K3: per-batch masked softmax
// ---------------------------------------------------------------------------
__global__ __launch_bounds__(256) void softmax_kernel(const int* __restrict__ tlen,
                                                      float* __restrict__ att_out) {
    int b = blockIdx.x;
    int tid = threadIdx.x;
    __shared__ float sl[NL];
    __shared__ float rbuf[256];
    int len = tlen[b];

    for (int l = tid; l < len; l += 256) sl[l] = g_logits[b * NL + l];
    __syncthreads();

    float mx = -INFINITY;
    for (int l = tid; l < len; l += 256) mx = fmaxf(mx, sl[l]);
    rbuf[tid] = mx;
    __syncthreads();
    for (int s = 128; s > 0; s >>= 1) {
        if (tid < s) rbuf[tid] = fmaxf(rbuf[tid], rbuf[tid + s]);
        __syncthreads();
    }
    mx = rbuf[0];
    __syncthreads();

    float sum = 0.0f;
    for (int l = tid; l < len; l += 256) {
        float e = fast_exp(sl[l] - mx);
        sl[l] = e;
        sum += e;
    }
    rbuf[tid] = sum;
    __syncthreads();
    for (int s = 128; s > 0; s >>= 1) {
        if (tid < s) rbuf[tid] = rbuf[tid] + rbuf[tid + s];
        __syncthreads();
    }
    float inv = 1.0f / rbuf[0];

    for (int l = tid; l < NL; l += 256)
        att_out[b * NL + l] = (l < len) ? sl[l] * inv : 0.0f;
}

// ---------------------------------------------------------------------------
// K4/K5: context partials + reduce
// ---------------------------------------------------------------------------
__global__ __launch_bounds__(256) void ctx_part_kernel(
    const float* __restrict__ ts, const float* __restrict__ att,
    const int* __restrict__ tlen) {
    int b = blockIdx.x;
    int c = blockIdx.y;
    int tid = threadIdx.x;
    float* out = g_ctx_part + ((size_t)c * NB + b) * 512;

    if (c * 128 >= tlen[b]) {
        out[tid] = 0.0f;
        out[tid + 256] = 0.0f;
        return;
    }

    __shared__ float sa[128];
    if (tid < 128) sa[tid] = att[b * NL + c * 128 + tid];
    __syncthreads();

    const float* base = ts + ((size_t)b * NL + c * 128) * 512;
    float a0 = 0.f, a1 = 0.f;
#pragma unroll 4
    for (int l = 0; l < 128; l++) {
        float wv = sa[l];
        a0 += wv * base[(size_t)l * 512 + tid];
        a1 += wv * base[(size_t)l * 512 + 256 + tid];
    }
    out[tid] = a0;
    out[tid + 256] = a1;
}

__global__ __launch_bounds__(512) void ctx_reduce_kernel(float* __restrict__ ctx) {
    int b = blockIdx.x;
    int f = threadIdx.x;
    float s = 0.0f;
#pragma unroll
    for (int c = 0; c < 32; c++) s += g_ctx_part[((size_t)c * NB + b) * 512 + f];
    ctx[b * 512 + f] = s;
}

// ---------------------------------------------------------------------------
// Launch
// ---------------------------------------------------------------------------
extern "C" void kernel_launch(void* const* d_in, const int* in_sizes, int n_in,
                              void* d_out, int out_size) {
    const float* ts  = (const float*)d_in[0];
    const float* ss  = (const float*)d_in[1];
    const float* cov = (const float*)d_in[2];
    const float* W1  = (const float*)d_in[3];
    const float* b1  = (const float*)d_in[4];
    const float* W2  = (const float*)d_in[5];
    const int*   tl  = (const int*)d_in[7];
    float* out = (float*)d_out;
    float* ctx_out = out;             // [32,512]
    float* att_out = out + NB * 512;  // [32,4096]

    cudaFuncSetAttribute(gemm_kernel,
                         cudaFuncAttributeMaxDynamicSharedMemorySize, SMEM_TOTAL);

    convB_kernel<<<NH, 512>>>(W1);
    base_kernel<<<NB, 512>>>(ss, W1, b1);
    gemm_kernel<<<1024, 256, SMEM_TOTAL>>>(ts, W1, W2, cov, tl);
    softmax_kernel<<<NB, 256>>>(tl, att_out);
    ctx_part_kernel<<<dim3(NB, 32), 256>>>(ts, att_out, tl);
    ctx_reduce_kernel<<<NB, 512>>>(ctx_out);
}

// round 11
// speedup vs baseline: 1.0201x; 1.0201x over previous
#include <cuda_runtime.h>
#include <cuda_fp16.h>
#include <math.h>
#include <stdint.h>

// ---------------------------------------------------------------------------
// Problem constants
// ---------------------------------------------------------------------------
#define NB   32
#define NL   4096
#define NH   512
#define NC   1025
#define MTOT (NB * NL)   // 131072

#define MT   128         // m rows per CTA
#define NST  16          // 4 h-tiles x 4 k-stages of 128

// SMEM layout
#define A_ROWB 1040                    // 512 fp16 + 16B pad
#define SM_A   0
#define A_BYTES (128 * A_ROWB)         // 133120
#define B_ROWB 272                     // 128 fp16 + 16B pad
#define B_TILE (128 * B_ROWB)          // 34816
#define SM_B   A_BYTES
#define SM_TAB (A_BYTES + 2 * B_TILE)  // 202752
// tables: w2[512] base[512] wcov[512] red[512] lac[128]
#define SMEM_TOTAL (SM_TAB + 8704)     // 211456

// ---------------------------------------------------------------------------
// Device scratch (static; no runtime allocation)
// ---------------------------------------------------------------------------
__device__ float g_base[NB * NH];
__device__ float g_logits[MTOT];
__device__ __half g_Bf[NH * 512];             // W1[:,0:512] fp16
__device__ float g_ctx_part[32 * NB * 512];
__device__ int g_work[1024];                  // compacted (b<<5)|tile list
__device__ int g_nwork;

// ---------------------------------------------------------------------------
// helpers
// ---------------------------------------------------------------------------
__device__ __forceinline__ uint32_t smem_u32(const void* p) {
    uint32_t a;
    asm("{ .reg .u64 t; cvta.to.shared.u64 t, %1; cvt.u32.u64 %0, t; }"
        : "=r"(a) : "l"(p));
    return a;
}

__device__ __forceinline__ void ldsm4(uint32_t addr, uint32_t& r0, uint32_t& r1,
                                      uint32_t& r2, uint32_t& r3) {
    asm volatile("ldmatrix.sync.aligned.m8n8.x4.shared.b16 {%0,%1,%2,%3}, [%4];"
                 : "=r"(r0), "=r"(r1), "=r"(r2), "=r"(r3) : "r"(addr));
}

__device__ __forceinline__ void mma16816(float* d, uint32_t a0, uint32_t a1,
                                         uint32_t a2, uint32_t a3, uint32_t b0,
                                         uint32_t b1) {
    asm volatile(
        "mma.sync.aligned.m16n8k16.row.col.f32.f16.f16.f32 "
        "{%0,%1,%2,%3}, {%4,%5,%6,%7}, {%8,%9}, {%0,%1,%2,%3};"
        : "+f"(d[0]), "+f"(d[1]), "+f"(d[2]), "+f"(d[3])
        : "r"(a0), "r"(a1), "r"(a2), "r"(a3), "r"(b0), "r"(b1));
}

__device__ __forceinline__ void cpasync16(uint32_t dst, const void* src) {
    asm volatile("cp.async.cg.shared.global [%0], [%1], 16;"
                 :: "r"(dst), "l"(src) : "memory");
}
#define CP_COMMIT() asm volatile("cp.async.commit_group;" ::: "memory")
#define CP_WAIT0()  asm volatile("cp.async.wait_group 0;" ::: "memory")

__device__ __forceinline__ float fast_tanh(float x) {
    float t = x * 2.885390081777927f;  // 2*log2(e)
    float e;
    asm("ex2.approx.f32 %0, %1;" : "=f"(e) : "f"(t));
    float r;
    asm("rcp.approx.f32 %0, %1;" : "=f"(r) : "f"(e + 1.0f));
    return 1.0f - 2.0f * r;
}
__device__ __forceinline__ float fast_exp(float x) {
    float t = x * 1.4426950408889634f;
    float e;
    asm("ex2.approx.f32 %0, %1;" : "=f"(e) : "f"(t));
    return e;
}
__device__ __forceinline__ uint32_t pack_h2(__half a, __half b) {
    __half2 v = __halves2half2(a, b);
    return *reinterpret_cast<uint32_t*>(&v);
}

// ---------------------------------------------------------------------------
// K-2: build compacted worklist of active (batch, tile) pairs. 1 warp.
// ---------------------------------------------------------------------------
__global__ void worklist_kernel(const int* __restrict__ tlen) {
    int b = threadIdx.x;  // 32 threads = 32 batches
    int nt = (tlen[b] + 127) >> 7;
    // exclusive prefix sum over 32 lanes
    int off = nt;
#pragma unroll
    for (int d = 1; d < 32; d <<= 1) {
        int v = __shfl_up_sync(0xffffffffu, off, d);
        if (b >= d) off += v;
    }
    int excl = off - nt;
    for (int t = 0; t < nt; t++) g_work[excl + t] = (b << 5) | t;
    if (b == 31) g_nwork = off;
}

// ---------------------------------------------------------------------------
// K-1b: W1[:,0:512] -> fp16
// ---------------------------------------------------------------------------
__global__ void convB_kernel(const float* __restrict__ W1) {
    int h = blockIdx.x;
    int k = threadIdx.x;
    g_Bf[h * 512 + k] = __float2half_rn(W1[(size_t)h * NC + k]);
}

// ---------------------------------------------------------------------------
// K0: base[b,h] = b1[h] + sum_c summary[b,c]*W1[h,512+c]  (exact fp32)
// ---------------------------------------------------------------------------
__global__ void base_kernel(const float* __restrict__ summary,
                            const float* __restrict__ W1,
                            const float* __restrict__ b1) {
    int b = blockIdx.x;
    int h = threadIdx.x;
    __shared__ float ss[512];
    ss[h] = summary[b * 512 + h];
    __syncthreads();
    const float* w = W1 + (size_t)h * NC + 512;
    float acc = b1[h];
#pragma unroll 8
    for (int c = 0; c < 512; c++) acc += ss[c] * w[c];
    g_base[b * NH + h] = acc;
}

// ---------------------------------------------------------------------------
// K1: HMMA GEMM (r9 internals: 512 threads, 16 warps 4m x 4n, flat 16-stage
// B pipeline, A conversion pipelined through first h-tile). Work-compacted.
// ---------------------------------------------------------------------------
__global__ __launch_bounds__(512, 1) void gemm_kernel(
    const float* __restrict__ ts, const float* __restrict__ W1,
    const float* __restrict__ W2, const float* __restrict__ coverage) {
    extern __shared__ char smem[];
    const uint32_t sb = smem_u32(smem);
    const int tid = threadIdx.x;
    const int lane = tid & 31;
    const int warp = tid >> 5;
    const int wm = warp & 3;   // m quadrant (32 rows)
    const int wn = warp >> 2;  // n quadrant (32 cols)

    if ((int)blockIdx.x >= g_nwork) return;
    const int wk = g_work[blockIdx.x];
    const int b = wk >> 5;
    const size_t m0 = (size_t)wk * MT;   // ((b*32)+tile)*128 == wk*128

    float* s_w2 = (float*)(smem + SM_TAB);            // 512
    float* s_base = (float*)(smem + SM_TAB + 2048);   // 512
    float* s_wcov = (float*)(smem + SM_TAB + 4096);   // 512
    float* s_red = (float*)(smem + SM_TAB + 6144);    // 128 x 4
    float* s_lac = (float*)(smem + SM_TAB + 8192);    // 128

    if (tid < 128) s_lac[tid] = 0.0f;

    // ---- prologue: B stage 0 (async) + A chunk 0 conversion + tables ----
    {
#pragma unroll
        for (int i = 0; i < 4; i++) {
            int e = tid + i * 512;
            int r = e >> 4, c = e & 15;
            cpasync16(sb + SM_B + (uint32_t)(r * B_ROWB + c * 16),
                      g_Bf + (size_t)r * 512 + c * 8);
        }
        CP_COMMIT();

        // A chunk 0: 4096 float4 slots (cols 0..127)
#pragma unroll
        for (int i = 0; i < 8; i++) {
            int e = tid + i * 512;
            int r = e >> 5, q = e & 31;
            float4 v = *(const float4*)(ts + (m0 + r) * 512 + q * 4);
            *(uint2*)(smem + r * A_ROWB + q * 8) = make_uint2(
                pack_h2(__float2half_rn(v.x), __float2half_rn(v.y)),
                pack_h2(__float2half_rn(v.z), __float2half_rn(v.w)));
        }

        s_w2[tid] = W2[tid];
        s_base[tid] = g_base[b * NH + tid];
        s_wcov[tid] = W1[(size_t)tid * NC + 1024];
        CP_WAIT0();
        __syncthreads();
    }

    const uint32_t aBase =
        sb + (uint32_t)((wm * 32 + (lane & 15)) * A_ROWB + (lane >> 4) * 16);
    const uint32_t bBase0 =
        sb + SM_B +
        (uint32_t)((wn * 32 + (lane & 7) + ((lane >> 4) & 1) * 8) * B_ROWB +
                   ((lane >> 3) & 1) * 16);

    float acc[2][4][4];
#pragma unroll
    for (int i = 0; i < 2; i++)
#pragma unroll
        for (int j = 0; j < 4; j++)
#pragma unroll
            for (int c = 0; c < 4; c++) acc[i][j][c] = 0.0f;

    const int cr = tid >> 4;   // B cp.async row base (0..31), +32 per i
    const int ccB = tid & 15;  // 16B chunk in B row

    for (int g = 0; g < NST; g++) {
        const uint32_t bo = (uint32_t)((g & 1) * B_TILE);

        if (g < NST - 1) {
            const int gn = g + 1;
            const int htn = gn >> 2, sn = gn & 3;
            const uint32_t nbo = (uint32_t)((gn & 1) * B_TILE);
#pragma unroll
            for (int i = 0; i < 4; i++) {
                int r = cr + i * 32;
                cpasync16(sb + SM_B + nbo + (uint32_t)(r * B_ROWB + ccB * 16),
                          g_Bf + (size_t)(htn * 128 + r) * 512 + sn * 128 +
                              ccB * 8);
            }
            CP_COMMIT();
        }

        // A prefetch (first h-tile only): chunk g+1, group 0
        const bool aPre = (g < 3);
        float4 av[4];
        if (aPre) {
#pragma unroll
            for (int i = 0; i < 4; i++) {
                int e = tid + i * 512;
                int r = e >> 5, q = e & 31;
                av[i] = *(const float4*)(ts + (m0 + r) * 512 + (g + 1) * 128 +
                                         q * 4);
            }
        }

        const uint32_t aOff = (uint32_t)((g & 3) * 256);
#pragma unroll
        for (int ks = 0; ks < 4; ks++) {
            uint32_t a0, a1, a2, a3, a4, a5, a6, a7;
            ldsm4(aBase + aOff + ks * 32, a0, a1, a2, a3);
            ldsm4(aBase + aOff + ks * 32 + 16 * A_ROWB, a4, a5, a6, a7);
#pragma unroll
            for (int tp = 0; tp < 2; tp++) {
                uint32_t b0, b1, b2, b3;
                ldsm4(bBase0 + bo + ks * 32 + tp * 16 * B_ROWB, b0, b1, b2, b3);
                mma16816(acc[0][2 * tp], a0, a1, a2, a3, b0, b1);
                mma16816(acc[0][2 * tp + 1], a0, a1, a2, a3, b2, b3);
                mma16816(acc[1][2 * tp], a4, a5, a6, a7, b0, b1);
                mma16816(acc[1][2 * tp + 1], a4, a5, a6, a7, b2, b3);
            }
        }

        if (aPre) {
#pragma unroll
            for (int i = 0; i < 4; i++) {
                int e = tid + i * 512;
                int r = e >> 5, q = e & 31;
                *(uint2*)(smem + r * A_ROWB + (g + 1) * 256 + q * 8) =
                    make_uint2(pack_h2(__float2half_rn(av[i].x),
                                       __float2half_rn(av[i].y)),
                               pack_h2(__float2half_rn(av[i].z),
                                       __float2half_rn(av[i].w)));
            }
#pragma unroll
            for (int i = 0; i < 4; i++) {
                int e = tid + (i + 4) * 512;
                int r = e >> 5, q = e & 31;
                av[i] = *(const float4*)(ts + (m0 + r) * 512 + (g + 1) * 128 +
                                         q * 4);
            }
        }

#pragma unroll
        for (int ks = 4; ks < 8; ks++) {
            uint32_t a0, a1, a2, a3, a4, a5, a6, a7;
            ldsm4(aBase + aOff + ks * 32, a0, a1, a2, a3);
            ldsm4(aBase + aOff + ks * 32 + 16 * A_ROWB, a4, a5, a6, a7);
#pragma unroll
            for (int tp = 0; tp < 2; tp++) {
                uint32_t b0, b1, b2, b3;
                ldsm4(bBase0 + bo + ks * 32 + tp * 16 * B_ROWB, b0, b1, b2, b3);
                mma16816(acc[0][2 * tp], a0, a1, a2, a3, b0, b1);
                mma16816(acc[0][2 * tp + 1], a0, a1, a2, a3, b2, b3);
                mma16816(acc[1][2 * tp], a4, a5, a6, a7, b0, b1);
                mma16816(acc[1][2 * tp + 1], a4, a5, a6, a7, b2, b3);
            }
        }

        if (aPre) {
#pragma unroll
            for (int i = 0; i < 4; i++) {
                int e = tid + (i + 4) * 512;
                int r = e >> 5, q = e & 31;
                *(uint2*)(smem + r * A_ROWB + (g + 1) * 256 + q * 8) =
                    make_uint2(pack_h2(__float2half_rn(av[i].x),
                                       __float2half_rn(av[i].y)),
                               pack_h2(__float2half_rn(av[i].z),
                                       __float2half_rn(av[i].w)));
            }
        }

        if ((g & 3) == 3) {
            const int h0 = (g >> 2) * 128;
#pragma unroll
            for (int tm = 0; tm < 2; tm++) {
#pragma unroll
                for (int rh = 0; rh < 2; rh++) {
                    int m_local = wm * 32 + tm * 16 + rh * 8 + (lane >> 2);
                    float cov = coverage[m0 + m_local];
                    float rs = 0.0f;
#pragma unroll
                    for (int tn = 0; tn < 4; tn++) {
                        int h = h0 + wn * 32 + tn * 8 + (lane & 3) * 2;
                        float p0 = acc[tm][tn][rh * 2 + 0] + s_base[h] +
                                   cov * s_wcov[h];
                        float p1 = acc[tm][tn][rh * 2 + 1] + s_base[h + 1] +
                                   cov * s_wcov[h + 1];
                        rs += fast_tanh(p0) * s_w2[h] +
                              fast_tanh(p1) * s_w2[h + 1];
                    }
                    rs += __shfl_xor_sync(0xffffffffu, rs, 1);
                    rs += __shfl_xor_sync(0xffffffffu, rs, 2);
                    if ((lane & 3) == 0) s_red[m_local * 4 + wn] = rs;
#pragma unroll
                    for (int tn = 0; tn < 4; tn++) {
                        acc[tm][tn][rh * 2 + 0] = 0.0f;
                        acc[tm][tn][rh * 2 + 1] = 0.0f;
                    }
                }
            }
            __syncthreads();
            if (tid < 128)
                s_lac[tid] += (s_red[tid * 4] + s_red[tid * 4 + 1]) +
                              (s_red[tid * 4 + 2] + s_red[tid * 4 + 3]);
        }

        if (g < NST - 1) CP_WAIT0();
        __syncthreads();
    }

    if (tid < 128) g_logits[m0 + tid] = s_lac[tid];
}

// ---------------------------------------------------------------------------
// K3: per-batch masked softmax
// ---------------------------------------------------------------------------
__global__ __launch_bounds__(256) void softmax_kernel(const int* __restrict__ tlen,
                                                      float* __restrict__ att_out) {
    int b = blockIdx.x;
    int tid = threadIdx.x;
    __shared__ float sl[NL];
    __shared__ float rbuf[256];
    int len = tlen[b];

    for (int l = tid; l < len; l += 256) sl[l] = g_logits[b * NL + l];
    __syncthreads();

    float mx = -INFINITY;
    for (int l = tid; l < len; l += 256) mx = fmaxf(mx, sl[l]);
    rbuf[tid] = mx;
    __syncthreads();
    for (int s = 128; s > 0; s >>= 1) {
        if (tid < s) rbuf[tid] = fmaxf(rbuf[tid], rbuf[tid + s]);
        __syncthreads();
    }
    mx = rbuf[0];
    __syncthreads();

    float sum = 0.0f;
    for (int l = tid; l < len; l += 256) {
        float e = fast_exp(sl[l] - mx);
        sl[l] = e;
        sum += e;
    }
    rbuf[tid] = sum;
    __syncthreads();
    for (int s = 128; s > 0; s >>= 1) {
        if (tid < s) rbuf[tid] = rbuf[tid] + rbuf[tid + s];
        __syncthreads();
    }
    float inv = 1.0f / rbuf[0];

    for (int l = tid; l < NL; l += 256)
        att_out[b * NL + l] = (l < len) ? sl[l] * inv : 0.0f;
}

// ---------------------------------------------------------------------------
// K4/K5: context partials (work-compacted) + masked reduce
// ---------------------------------------------------------------------------
__global__ __launch_bounds__(256) void ctx_part_kernel(
    const float* __restrict__ ts, const float* __restrict__ att) {
    if ((int)blockIdx.x >= g_nwork) return;
    int wk = g_work[blockIdx.x];
    int b = wk >> 5;
    int c = wk & 31;
    int tid = threadIdx.x;
    float* out = g_ctx_part + ((size_t)c * NB + b) * 512;

    __shared__ float sa[128];
    if (tid < 128) sa[tid] = att[b * NL + c * 128 + tid];
    __syncthreads();

    const float* base = ts + ((size_t)b * NL + c * 128) * 512;
    float a0 = 0.f, a1 = 0.f;
#pragma unroll 4
    for (int l = 0; l < 128; l++) {
        float wv = sa[l];
        a0 += wv * base[(size_t)l * 512 + tid];
        a1 += wv * base[(size_t)l * 512 + 256 + tid];
    }
    out[tid] = a0;
    out[tid + 256] = a1;
}

__global__ __launch_bounds__(512) void ctx_reduce_kernel(
    const int* __restrict__ tlen, float* __restrict__ ctx) {
    int b = blockIdx.x;
    int f = threadIdx.x;
    int nt = (tlen[b] + 127) >> 7;
    float s = 0.0f;
    for (int c = 0; c < nt; c++)
        s += g_ctx_part[((size_t)c * NB + b) * 512 + f];
    ctx[b * 512 + f] = s;
}

// ---------------------------------------------------------------------------
// Launch
// ---------------------------------------------------------------------------
extern "C" void kernel_launch(void* const* d_in, const int* in_sizes, int n_in,
                              void* d_out, int out_size) {
    const float* ts  = (const float*)d_in[0];
    const float* ss  = (const float*)d_in[1];
    const float* cov = (const float*)d_in[2];
    const float* W1  = (const float*)d_in[3];
    const float* b1  = (const float*)d_in[4];
    const float* W2  = (const float*)d_in[5];
    const int*   tl  = (const int*)d_in[7];
    float* out = (float*)d_out;
    float* ctx_out = out;             // [32,512]
    float* att_out = out + NB * 512;  // [32,4096]

    cudaFuncSetAttribute(gemm_kernel,
                         cudaFuncAttributeMaxDynamicSharedMemorySize, SMEM_TOTAL);

    worklist_kernel<<<1, 32>>>(tl);
    convB_kernel<<<NH, 512>>>(W1);
    base_kernel<<<NB, 512>>>(ss, W1, b1);
    gemm_kernel<<<1024, 512, SMEM_TOTAL>>>(ts, W1, W2, cov);
    softmax_kernel<<<NB, 256>>>(tl, att_out);
    ctx_part_kernel<<<1024, 256>>>(ts, att_out);
    ctx_reduce_kernel<<<NB, 512>>>(tl, ctx_out);
}

// round 12
// speedup vs baseline: 1.0589x; 1.0379x over previous
#include <cuda_runtime.h>
#include <cuda_fp16.h>
#include <math.h>
#include <stdint.h>

// ---------------------------------------------------------------------------
// Problem constants
// ---------------------------------------------------------------------------
#define NB   32
#define NL   4096
#define NH   512
#define NC   1025
#define MTOT (NB * NL)   // 131072

#define MT   128         // m rows per CTA
#define NST  16          // 4 h-tiles x 4 k-stages of 128

// SMEM layout
#define A_ROWB 1040                    // 512 fp16 + 16B pad
#define SM_A   0
#define A_BYTES (128 * A_ROWB)         // 133120
#define B_ROWB 272                     // 128 fp16 + 16B pad
#define B_TILE (128 * B_ROWB)          // 34816
#define SM_B   A_BYTES
#define SM_TAB (A_BYTES + 2 * B_TILE)  // 202752
// tables: w2[512] base[512] wcov[512] red[512]
#define SMEM_TOTAL (SM_TAB + 8192)     // 210944

// ---------------------------------------------------------------------------
// Device scratch (static; no runtime allocation)
// ---------------------------------------------------------------------------
__device__ float g_base[NB * NH];
__device__ float g_logits[MTOT];
__device__ __half g_Bf[NH * 512];             // W1[:,0:512] fp16
__device__ float g_ctx_part[32 * NB * 512];
__device__ int g_work[1024];                  // compacted (b<<5)|tile list
__device__ int g_nwork;

// ---------------------------------------------------------------------------
// helpers
// ---------------------------------------------------------------------------
__device__ __forceinline__ uint32_t smem_u32(const void* p) {
    uint32_t a;
    asm("{ .reg .u64 t; cvta.to.shared.u64 t, %1; cvt.u32.u64 %0, t; }"
        : "=r"(a) : "l"(p));
    return a;
}

__device__ __forceinline__ void ldsm4(uint32_t addr, uint32_t& r0, uint32_t& r1,
                                      uint32_t& r2, uint32_t& r3) {
    asm volatile("ldmatrix.sync.aligned.m8n8.x4.shared.b16 {%0,%1,%2,%3}, [%4];"
                 : "=r"(r0), "=r"(r1), "=r"(r2), "=r"(r3) : "r"(addr));
}

__device__ __forceinline__ void mma16816(float* d, uint32_t a0, uint32_t a1,
                                         uint32_t a2, uint32_t a3, uint32_t b0,
                                         uint32_t b1) {
    asm volatile(
        "mma.sync.aligned.m16n8k16.row.col.f32.f16.f16.f32 "
        "{%0,%1,%2,%3}, {%4,%5,%6,%7}, {%8,%9}, {%0,%1,%2,%3};"
        : "+f"(d[0]), "+f"(d[1]), "+f"(d[2]), "+f"(d[3])
        : "r"(a0), "r"(a1), "r"(a2), "r"(a3), "r"(b0), "r"(b1));
}

__device__ __forceinline__ void cpasync16(uint32_t dst, const void* src) {
    asm volatile("cp.async.cg.shared.global [%0], [%1], 16;"
                 :: "r"(dst), "l"(src) : "memory");
}
#define CP_COMMIT() asm volatile("cp.async.commit_group;" ::: "memory")
#define CP_WAIT0()  asm volatile("cp.async.wait_group 0;" ::: "memory")

__device__ __forceinline__ float fast_tanh(float x) {
    float t = x * 2.885390081777927f;  // 2*log2(e)
    float e;
    asm("ex2.approx.f32 %0, %1;" : "=f"(e) : "f"(t));
    float r;
    asm("rcp.approx.f32 %0, %1;" : "=f"(r) : "f"(e + 1.0f));
    return 1.0f - 2.0f * r;
}
__device__ __forceinline__ float fast_exp(float x) {
    float t = x * 1.4426950408889634f;
    float e;
    asm("ex2.approx.f32 %0, %1;" : "=f"(e) : "f"(t));
    return e;
}
__device__ __forceinline__ uint32_t pack_h2(__half a, __half b) {
    __half2 v = __halves2half2(a, b);
    return *reinterpret_cast<uint32_t*>(&v);
}

// ---------------------------------------------------------------------------
// K0: fused prep. Blocks 0..511: convB row. Blocks 512..543: base[b,:].
// Block 544: worklist. One launch instead of three.
// ---------------------------------------------------------------------------
__global__ __launch_bounds__(512) void prep_kernel(
    const float* __restrict__ W1, const float* __restrict__ summary,
    const float* __restrict__ b1, const int* __restrict__ tlen) {
    int blk = blockIdx.x;
    int tid = threadIdx.x;

    if (blk < 512) {
        // convB: W1[blk, 0:512] -> fp16
        g_Bf[blk * 512 + tid] = __float2half_rn(W1[(size_t)blk * NC + tid]);
    } else if (blk < 544) {
        // base[b,h]
        int b = blk - 512;
        __shared__ float ss[512];
        ss[tid] = summary[b * 512 + tid];
        __syncthreads();
        const float* w = W1 + (size_t)tid * NC + 512;
        float acc = b1[tid];
#pragma unroll 8
        for (int c = 0; c < 512; c++) acc += ss[c] * w[c];
        g_base[b * NH + tid] = acc;
    } else if (tid < 32) {
        // worklist: compacted (b<<5)|tile
        int nt = (tlen[tid] + 127) >> 7;
        int off = nt;
#pragma unroll
        for (int d = 1; d < 32; d <<= 1) {
            int v = __shfl_up_sync(0xffffffffu, off, d);
            if (tid >= d) off += v;
        }
        int excl = off - nt;
        for (int t = 0; t < nt; t++) g_work[excl + t] = (tid << 5) | t;
        if (tid == 31) g_nwork = off;
    }
}

// ---------------------------------------------------------------------------
// K1: HMMA GEMM. 512 threads, 16 warps 4m x 4n. A resident (converted in a
// pipeline through the first h-tile), flat 16-stage B pipeline, register-
// accumulated logit partials (single smem reduction at the end).
// ---------------------------------------------------------------------------
__global__ __launch_bounds__(512, 1) void gemm_kernel(
    const float* __restrict__ ts, const float* __restrict__ W1,
    const float* __restrict__ W2, const float* __restrict__ coverage) {
    extern __shared__ char smem[];
    const uint32_t sb = smem_u32(smem);
    const int tid = threadIdx.x;
    const int lane = tid & 31;
    const int warp = tid >> 5;
    const int wm = warp & 3;   // m quadrant (32 rows)
    const int wn = warp >> 2;  // n quadrant (32 cols)

    if ((int)blockIdx.x >= g_nwork) return;
    const int wk = g_work[blockIdx.x];
    const int b = wk >> 5;
    const size_t m0 = (size_t)wk * MT;

    float* s_w2 = (float*)(smem + SM_TAB);            // 512
    float* s_base = (float*)(smem + SM_TAB + 2048);   // 512
    float* s_wcov = (float*)(smem + SM_TAB + 4096);   // 512
    float* s_red = (float*)(smem + SM_TAB + 6144);    // 128 x 4

    // ---- prologue: B stage 0 (async) + A chunk 0 conversion + tables ----
    {
#pragma unroll
        for (int i = 0; i < 4; i++) {
            int e = tid + i * 512;
            int r = e >> 4, c = e & 15;
            cpasync16(sb + SM_B + (uint32_t)(r * B_ROWB + c * 16),
                      g_Bf + (size_t)r * 512 + c * 8);
        }
        CP_COMMIT();

        // A chunk 0: 4096 float4 slots (cols 0..127)
#pragma unroll
        for (int i = 0; i < 8; i++) {
            int e = tid + i * 512;
            int r = e >> 5, q = e & 31;
            float4 v = *(const float4*)(ts + (m0 + r) * 512 + q * 4);
            *(uint2*)(smem + r * A_ROWB + q * 8) = make_uint2(
                pack_h2(__float2half_rn(v.x), __float2half_rn(v.y)),
                pack_h2(__float2half_rn(v.z), __float2half_rn(v.w)));
        }

        s_w2[tid] = W2[tid];
        s_base[tid] = g_base[b * NH + tid];
        s_wcov[tid] = W1[(size_t)tid * NC + 1024];
        CP_WAIT0();
        __syncthreads();
    }

    const uint32_t aBase =
        sb + (uint32_t)((wm * 32 + (lane & 15)) * A_ROWB + (lane >> 4) * 16);
    const uint32_t bBase0 =
        sb + SM_B +
        (uint32_t)((wn * 32 + (lane & 7) + ((lane >> 4) & 1) * 8) * B_ROWB +
                   ((lane >> 3) & 1) * 16);

    float acc[2][4][4];
#pragma unroll
    for (int i = 0; i < 2; i++)
#pragma unroll
        for (int j = 0; j < 4; j++)
#pragma unroll
            for (int c = 0; c < 4; c++) acc[i][j][c] = 0.0f;

    // register logit partials + hoisted coverage
    float rsum[2][2] = {{0.0f, 0.0f}, {0.0f, 0.0f}};
    float covr[2][2];
#pragma unroll
    for (int tm = 0; tm < 2; tm++)
#pragma unroll
        for (int rh = 0; rh < 2; rh++)
            covr[tm][rh] =
                coverage[m0 + wm * 32 + tm * 16 + rh * 8 + (lane >> 2)];

    const int cr = tid >> 4;   // B cp.async row base (0..31), +32 per i
    const int ccB = tid & 15;  // 16B chunk in B row

    for (int g = 0; g < NST; g++) {
        const uint32_t bo = (uint32_t)((g & 1) * B_TILE);

        if (g < NST - 1) {
            const int gn = g + 1;
            const int htn = gn >> 2, sn = gn & 3;
            const uint32_t nbo = (uint32_t)((gn & 1) * B_TILE);
#pragma unroll
            for (int i = 0; i < 4; i++) {
                int r = cr + i * 32;
                cpasync16(sb + SM_B + nbo + (uint32_t)(r * B_ROWB + ccB * 16),
                          g_Bf + (size_t)(htn * 128 + r) * 512 + sn * 128 +
                              ccB * 8);
            }
            CP_COMMIT();
        }

        // A prefetch (first h-tile only): chunk g+1, group 0
        const bool aPre = (g < 3);
        float4 av[4];
        if (aPre) {
#pragma unroll
            for (int i = 0; i < 4; i++) {
                int e = tid + i * 512;
                int r = e >> 5, q = e & 31;
                av[i] = *(const float4*)(ts + (m0 + r) * 512 + (g + 1) * 128 +
                                         q * 4);
            }
        }

        const uint32_t aOff = (uint32_t)((g & 3) * 256);
#pragma unroll
        for (int ks = 0; ks < 4; ks++) {
            uint32_t a0, a1, a2, a3, a4, a5, a6, a7;
            ldsm4(aBase + aOff + ks * 32, a0, a1, a2, a3);
            ldsm4(aBase + aOff + ks * 32 + 16 * A_ROWB, a4, a5, a6, a7);
#pragma unroll
            for (int tp = 0; tp < 2; tp++) {
                uint32_t b0, b1, b2, b3;
                ldsm4(bBase0 + bo + ks * 32 + tp * 16 * B_ROWB, b0, b1, b2, b3);
                mma16816(acc[0][2 * tp], a0, a1, a2, a3, b0, b1);
                mma16816(acc[0][2 * tp + 1], a0, a1, a2, a3, b2, b3);
                mma16816(acc[1][2 * tp], a4, a5, a6, a7, b0, b1);
                mma16816(acc[1][2 * tp + 1], a4, a5, a6, a7, b2, b3);
            }
        }

        if (aPre) {
#pragma unroll
            for (int i = 0; i < 4; i++) {
                int e = tid + i * 512;
                int r = e >> 5, q = e & 31;
                *(uint2*)(smem + r * A_ROWB + (g + 1) * 256 + q * 8) =
                    make_uint2(pack_h2(__float2half_rn(av[i].x),
                                       __float2half_rn(av[i].y)),
                               pack_h2(__float2half_rn(av[i].z),
                                       __float2half_rn(av[i].w)));
            }
#pragma unroll
            for (int i = 0; i < 4; i++) {
                int e = tid + (i + 4) * 512;
                int r = e >> 5, q = e & 31;
                av[i] = *(const float4*)(ts + (m0 + r) * 512 + (g + 1) * 128 +
                                         q * 4);
            }
        }

#pragma unroll
        for (int ks = 4; ks < 8; ks++) {
            uint32_t a0, a1, a2, a3, a4, a5, a6, a7;
            ldsm4(aBase + aOff + ks * 32, a0, a1, a2, a3);
            ldsm4(aBase + aOff + ks * 32 + 16 * A_ROWB, a4, a5, a6, a7);
#pragma unroll
            for (int tp = 0; tp < 2; tp++) {
                uint32_t b0, b1, b2, b3;
                ldsm4(bBase0 + bo + ks * 32 + tp * 16 * B_ROWB, b0, b1, b2, b3);
                mma16816(acc[0][2 * tp], a0, a1, a2, a3, b0, b1);
                mma16816(acc[0][2 * tp + 1], a0, a1, a2, a3, b2, b3);
                mma16816(acc[1][2 * tp], a4, a5, a6, a7, b0, b1);
                mma16816(acc[1][2 * tp + 1], a4, a5, a6, a7, b2, b3);
            }
        }

        if (aPre) {
#pragma unroll
            for (int i = 0; i < 4; i++) {
                int e = tid + (i + 4) * 512;
                int r = e >> 5, q = e & 31;
                *(uint2*)(smem + r * A_ROWB + (g + 1) * 256 + q * 8) =
                    make_uint2(pack_h2(__float2half_rn(av[i].x),
                                       __float2half_rn(av[i].y)),
                               pack_h2(__float2half_rn(av[i].z),
                                       __float2half_rn(av[i].w)));
            }
        }

        // h-tile boundary: fold into register partials (no smem, no syncs)
        if ((g & 3) == 3) {
            const int h0 = (g >> 2) * 128;
#pragma unroll
            for (int tm = 0; tm < 2; tm++) {
#pragma unroll
                for (int rh = 0; rh < 2; rh++) {
                    float cov = covr[tm][rh];
                    float rs = 0.0f;
#pragma unroll
                    for (int tn = 0; tn < 4; tn++) {
                        int h = h0 + wn * 32 + tn * 8 + (lane & 3) * 2;
                        float p0 = acc[tm][tn][rh * 2 + 0] + s_base[h] +
                                   cov * s_wcov[h];
                        float p1 = acc[tm][tn][rh * 2 + 1] + s_base[h + 1] +
                                   cov * s_wcov[h + 1];
                        rs += fast_tanh(p0) * s_w2[h] +
                              fast_tanh(p1) * s_w2[h + 1];
                    }
                    rsum[tm][rh] += rs;
#pragma unroll
                    for (int tn = 0; tn < 4; tn++) {
                        acc[tm][tn][rh * 2 + 0] = 0.0f;
                        acc[tm][tn][rh * 2 + 1] = 0.0f;
                    }
                }
            }
        }

        if (g < NST - 1) CP_WAIT0();
        __syncthreads();
    }

    // ---- final logit reduction (once) ----
#pragma unroll
    for (int tm = 0; tm < 2; tm++) {
#pragma unroll
        for (int rh = 0; rh < 2; rh++) {
            float rs = rsum[tm][rh];
            rs += __shfl_xor_sync(0xffffffffu, rs, 1);
            rs += __shfl_xor_sync(0xffffffffu, rs, 2);
            int m_local = wm * 32 + tm * 16 + rh * 8 + (lane >> 2);
            if ((lane & 3) == 0) s_red[m_local * 4 + wn] = rs;
        }
    }
    __syncthreads();
    if (tid < 128)
        g_logits[m0 + tid] = (s_red[tid * 4] + s_red[tid * 4 + 1]) +
                             (s_red[tid * 4 + 2] + s_red[tid * 4 + 3]);
}

// ---------------------------------------------------------------------------
// K3: per-batch masked softmax (512 threads)
// ---------------------------------------------------------------------------
__global__ __launch_bounds__(512) void softmax_kernel(const int* __restrict__ tlen,
                                                      float* __restrict__ att_out) {
    int b = blockIdx.x;
    int tid = threadIdx.x;
    __shared__ float sl[NL];
    __shared__ float rbuf[512];
    int len = tlen[b];

    for (int l = tid; l < len; l += 512) sl[l] = g_logits[b * NL + l];
    __syncthreads();

    float mx = -INFINITY;
    for (int l = tid; l < len; l += 512) mx = fmaxf(mx, sl[l]);
    rbuf[tid] = mx;
    __syncthreads();
    for (int s = 256; s > 0; s >>= 1) {
        if (tid < s) rbuf[tid] = fmaxf(rbuf[tid], rbuf[tid + s]);
        __syncthreads();
    }
    mx = rbuf[0];
    __syncthreads();

    float sum = 0.0f;
    for (int l = tid; l < len; l += 512) {
        float e = fast_exp(sl[l] - mx);
        sl[l] = e;
        sum += e;
    }
    rbuf[tid] = sum;
    __syncthreads();
    for (int s = 256; s > 0; s >>= 1) {
        if (tid < s) rbuf[tid] = rbuf[tid] + rbuf[tid + s];
        __syncthreads();
    }
    float inv = 1.0f / rbuf[0];

    for (int l = tid; l < NL; l += 512)
        att_out[b * NL + l] = (l < len) ? sl[l] * inv : 0.0f;
}

// ---------------------------------------------------------------------------
// K4/K5: context partials (work-compacted) + masked reduce
// ---------------------------------------------------------------------------
__global__ __launch_bounds__(256) void ctx_part_kernel(
    const float* __restrict__ ts, const float* __restrict__ att) {
    if ((int)blockIdx.x >= g_nwork) return;
    int wk = g_work[blockIdx.x];
    int b = wk >> 5;
    int c = wk & 31;
    int tid = threadIdx.x;
    float* out = g_ctx_part + ((size_t)c * NB + b) * 512;

    __shared__ float sa[128];
    if (tid < 128) sa[tid] = att[b * NL + c * 128 + tid];
    __syncthreads();

    const float* base = ts + ((size_t)b * NL + c * 128) * 512;
    float a0 = 0.f, a1 = 0.f;
#pragma unroll 4
    for (int l = 0; l < 128; l++) {
        float wv = sa[l];
        a0 += wv * base[(size_t)l * 512 + tid];
        a1 += wv * base[(size_t)l * 512 + 256 + tid];
    }
    out[tid] = a0;
    out[tid + 256] = a1;
}

__global__ __launch_bounds__(512) void ctx_reduce_kernel(
    const int* __restrict__ tlen, float* __restrict__ ctx) {
    int b = blockIdx.x;
    int f = threadIdx.x;
    int nt = (tlen[b] + 127) >> 7;
    float s = 0.0f;
    for (int c = 0; c < nt; c++)
        s += g_ctx_part[((size_t)c * NB + b) * 512 + f];
    ctx[b * 512 + f] = s;
}

// ---------------------------------------------------------------------------
// Launch
// ---------------------------------------------------------------------------
extern "C" void kernel_launch(void* const* d_in, const int* in_sizes, int n_in,
                              void* d_out, int out_size) {
    const float* ts  = (const float*)d_in[0];
    const float* ss  = (const float*)d_in[1];
    const float* cov = (const float*)d_in[2];
    const float* W1  = (const float*)d_in[3];
    const float* b1  = (const float*)d_in[4];
    const float* W2  = (const float*)d_in[5];
    const int*   tl  = (const int*)d_in[7];
    float* out = (float*)d_out;
    float* ctx_out = out;             // [32,512]
    float* att_out = out + NB * 512;  // [32,4096]

    cudaFuncSetAttribute(gemm_kernel,
                         cudaFuncAttributeMaxDynamicSharedMemorySize, SMEM_TOTAL);

    prep_kernel<<<545, 512>>>(W1, ss, b1, tl);
    gemm_kernel<<<1024, 512, SMEM_TOTAL>>>(ts, W1, W2, cov);
    softmax_kernel<<<NB, 512>>>(tl, att_out);
    ctx_part_kernel<<<1024, 256>>>(ts, att_out);
    ctx_reduce_kernel<<<NB, 512>>>(tl, ctx_out);
}

// round 13
// speedup vs baseline: 1.0657x; 1.0065x over previous
#include <cuda_runtime.h>
#include <cuda_fp16.h>
#include <math.h>
#include <stdint.h>

// ---------------------------------------------------------------------------
// Problem constants
// ---------------------------------------------------------------------------
#define NB   32
#define NL   4096
#define NH   512
#define NC   1025
#define MTOT (NB * NL)   // 131072

#define MT   128         // m rows per CTA
#define NST  16          // 4 h-tiles x 4 k-stages of 128

// SMEM layout
#define A_ROWB 1040                    // 512 fp16 + 16B pad
#define SM_A   0
#define A_BYTES (128 * A_ROWB)         // 133120
#define B_ROWB 272                     // 128 fp16 + 16B pad
#define B_TILE (128 * B_ROWB)          // 34816
#define SM_B   A_BYTES
#define SM_TAB (A_BYTES + 2 * B_TILE)  // 202752
// tables: w2[512] base[512] wcov[512] red[512]
#define SMEM_TOTAL (SM_TAB + 8192)     // 210944

// ---------------------------------------------------------------------------
// Device scratch (static; no runtime allocation)
// ---------------------------------------------------------------------------
__device__ float g_base[NB * NH];
__device__ float g_logits[MTOT];
__device__ __half g_Bf[NH * 512];             // W1[:,0:512] fp16
__device__ float g_ctx_part[32 * NB * 512];
__device__ int g_work[1024];                  // compacted (b<<5)|tile list
__device__ int g_nwork;

// ---------------------------------------------------------------------------
// helpers
// ---------------------------------------------------------------------------
__device__ __forceinline__ uint32_t smem_u32(const void* p) {
    uint32_t a;
    asm("{ .reg .u64 t; cvta.to.shared.u64 t, %1; cvt.u32.u64 %0, t; }"
        : "=r"(a) : "l"(p));
    return a;
}

__device__ __forceinline__ void ldsm4(uint32_t addr, uint32_t& r0, uint32_t& r1,
                                      uint32_t& r2, uint32_t& r3) {
    asm volatile("ldmatrix.sync.aligned.m8n8.x4.shared.b16 {%0,%1,%2,%3}, [%4];"
                 : "=r"(r0), "=r"(r1), "=r"(r2), "=r"(r3) : "r"(addr));
}

__device__ __forceinline__ void mma16816(float* d, uint32_t a0, uint32_t a1,
                                         uint32_t a2, uint32_t a3, uint32_t b0,
                                         uint32_t b1) {
    asm volatile(
        "mma.sync.aligned.m16n8k16.row.col.f32.f16.f16.f32 "
        "{%0,%1,%2,%3}, {%4,%5,%6,%7}, {%8,%9}, {%0,%1,%2,%3};"
        : "+f"(d[0]), "+f"(d[1]), "+f"(d[2]), "+f"(d[3])
        : "r"(a0), "r"(a1), "r"(a2), "r"(a3), "r"(b0), "r"(b1));
}

__device__ __forceinline__ void cpasync16(uint32_t dst, const void* src) {
    asm volatile("cp.async.cg.shared.global [%0], [%1], 16;"
                 :: "r"(dst), "l"(src) : "memory");
}
#define CP_COMMIT() asm volatile("cp.async.commit_group;" ::: "memory")
#define CP_WAIT0()  asm volatile("cp.async.wait_group 0;" ::: "memory")

__device__ __forceinline__ float fast_tanh(float x) {
    float t = x * 2.885390081777927f;  // 2*log2(e)
    float e;
    asm("ex2.approx.f32 %0, %1;" : "=f"(e) : "f"(t));
    float r;
    asm("rcp.approx.f32 %0, %1;" : "=f"(r) : "f"(e + 1.0f));
    return 1.0f - 2.0f * r;
}
__device__ __forceinline__ float fast_exp(float x) {
    float t = x * 1.4426950408889634f;
    float e;
    asm("ex2.approx.f32 %0, %1;" : "=f"(e) : "f"(t));
    return e;
}
__device__ __forceinline__ uint32_t pack_h2(__half a, __half b) {
    __half2 v = __halves2half2(a, b);
    return *reinterpret_cast<uint32_t*>(&v);
}

// ---------------------------------------------------------------------------
// K0: fused prep. Blocks 0..511: convB row. Blocks 512..543: base[b,:].
// Block 544: worklist.
// ---------------------------------------------------------------------------
__global__ __launch_bounds__(512) void prep_kernel(
    const float* __restrict__ W1, const float* __restrict__ summary,
    const float* __restrict__ b1, const int* __restrict__ tlen) {
    int blk = blockIdx.x;
    int tid = threadIdx.x;

    if (blk < 512) {
        g_Bf[blk * 512 + tid] = __float2half_rn(W1[(size_t)blk * NC + tid]);
    } else if (blk < 544) {
        int b = blk - 512;
        __shared__ float ss[512];
        ss[tid] = summary[b * 512 + tid];
        __syncthreads();
        const float* w = W1 + (size_t)tid * NC + 512;
        float acc = b1[tid];
#pragma unroll 8
        for (int c = 0; c < 512; c++) acc += ss[c] * w[c];
        g_base[b * NH + tid] = acc;
    } else if (tid < 32) {
        int nt = (tlen[tid] + 127) >> 7;
        int off = nt;
#pragma unroll
        for (int d = 1; d < 32; d <<= 1) {
            int v = __shfl_up_sync(0xffffffffu, off, d);
            if (tid >= d) off += v;
        }
        int excl = off - nt;
        for (int t = 0; t < nt; t++) g_work[excl + t] = (tid << 5) | t;
        if (tid == 31) g_nwork = off;
    }
}

// ---------------------------------------------------------------------------
// K1: HMMA GEMM. 512 threads, 16 warps 4m x 4n. A resident (converted in a
// pipeline through the first h-tile), flat 16-stage B pipeline, register-
// accumulated logit partials (single smem reduction at the end).
// ---------------------------------------------------------------------------
__global__ __launch_bounds__(512, 1) void gemm_kernel(
    const float* __restrict__ ts, const float* __restrict__ W1,
    const float* __restrict__ W2, const float* __restrict__ coverage) {
    extern __shared__ char smem[];
    const uint32_t sb = smem_u32(smem);
    const int tid = threadIdx.x;
    const int lane = tid & 31;
    const int warp = tid >> 5;
    const int wm = warp & 3;   // m quadrant (32 rows)
    const int wn = warp >> 2;  // n quadrant (32 cols)

    if ((int)blockIdx.x >= g_nwork) return;
    const int wk = g_work[blockIdx.x];
    const int b = wk >> 5;
    const size_t m0 = (size_t)wk * MT;

    float* s_w2 = (float*)(smem + SM_TAB);            // 512
    float* s_base = (float*)(smem + SM_TAB + 2048);   // 512
    float* s_wcov = (float*)(smem + SM_TAB + 4096);   // 512
    float* s_red = (float*)(smem + SM_TAB + 6144);    // 128 x 4

    // ---- prologue: B stage 0 (async) + A chunk 0 conversion + tables ----
    {
#pragma unroll
        for (int i = 0; i < 4; i++) {
            int e = tid + i * 512;
            int r = e >> 4, c = e & 15;
            cpasync16(sb + SM_B + (uint32_t)(r * B_ROWB + c * 16),
                      g_Bf + (size_t)r * 512 + c * 8);
        }
        CP_COMMIT();

#pragma unroll
        for (int i = 0; i < 8; i++) {
            int e = tid + i * 512;
            int r = e >> 5, q = e & 31;
            float4 v = *(const float4*)(ts + (m0 + r) * 512 + q * 4);
            *(uint2*)(smem + r * A_ROWB + q * 8) = make_uint2(
                pack_h2(__float2half_rn(v.x), __float2half_rn(v.y)),
                pack_h2(__float2half_rn(v.z), __float2half_rn(v.w)));
        }

        s_w2[tid] = W2[tid];
        s_base[tid] = g_base[b * NH + tid];
        s_wcov[tid] = W1[(size_t)tid * NC + 1024];
        CP_WAIT0();
        __syncthreads();
    }

    const uint32_t aBase =
        sb + (uint32_t)((wm * 32 + (lane & 15)) * A_ROWB + (lane >> 4) * 16);
    const uint32_t bBase0 =
        sb + SM_B +
        (uint32_t)((wn * 32 + (lane & 7) + ((lane >> 4) & 1) * 8) * B_ROWB +
                   ((lane >> 3) & 1) * 16);

    float acc[2][4][4];
#pragma unroll
    for (int i = 0; i < 2; i++)
#pragma unroll
        for (int j = 0; j < 4; j++)
#pragma unroll
            for (int c = 0; c < 4; c++) acc[i][j][c] = 0.0f;

    float rsum[2][2] = {{0.0f, 0.0f}, {0.0f, 0.0f}};
    float covr[2][2];
#pragma unroll
    for (int tm = 0; tm < 2; tm++)
#pragma unroll
        for (int rh = 0; rh < 2; rh++)
            covr[tm][rh] =
                coverage[m0 + wm * 32 + tm * 16 + rh * 8 + (lane >> 2)];

    const int cr = tid >> 4;   // B cp.async row base (0..31), +32 per i
    const int ccB = tid & 15;  // 16B chunk in B row

    for (int g = 0; g < NST; g++) {
        const uint32_t bo = (uint32_t)((g & 1) * B_TILE);

        if (g < NST - 1) {
            const int gn = g + 1;
            const int htn = gn >> 2, sn = gn & 3;
            const uint32_t nbo = (uint32_t)((gn & 1) * B_TILE);
#pragma unroll
            for (int i = 0; i < 4; i++) {
                int r = cr + i * 32;
                cpasync16(sb + SM_B + nbo + (uint32_t)(r * B_ROWB + ccB * 16),
                          g_Bf + (size_t)(htn * 128 + r) * 512 + sn * 128 +
                              ccB * 8);
            }
            CP_COMMIT();
        }

        const bool aPre = (g < 3);
        float4 av[4];
        if (aPre) {
#pragma unroll
            for (int i = 0; i < 4; i++) {
                int e = tid + i * 512;
                int r = e >> 5, q = e & 31;
                av[i] = *(const float4*)(ts + (m0 + r) * 512 + (g + 1) * 128 +
                                         q * 4);
            }
        }

        const uint32_t aOff = (uint32_t)((g & 3) * 256);
#pragma unroll
        for (int ks = 0; ks < 4; ks++) {
            uint32_t a0, a1, a2, a3, a4, a5, a6, a7;
            ldsm4(aBase + aOff + ks * 32, a0, a1, a2, a3);
            ldsm4(aBase + aOff + ks * 32 + 16 * A_ROWB, a4, a5, a6, a7);
#pragma unroll
            for (int tp = 0; tp < 2; tp++) {
                uint32_t b0, b1, b2, b3;
                ldsm4(bBase0 + bo + ks * 32 + tp * 16 * B_ROWB, b0, b1, b2, b3);
                mma16816(acc[0][2 * tp], a0, a1, a2, a3, b0, b1);
                mma16816(acc[0][2 * tp + 1], a0, a1, a2, a3, b2, b3);
                mma16816(acc[1][2 * tp], a4, a5, a6, a7, b0, b1);
                mma16816(acc[1][2 * tp + 1], a4, a5, a6, a7, b2, b3);
            }
        }

        if (aPre) {
#pragma unroll
            for (int i = 0; i < 4; i++) {
                int e = tid + i * 512;
                int r = e >> 5, q = e & 31;
                *(uint2*)(smem + r * A_ROWB + (g + 1) * 256 + q * 8) =
                    make_uint2(pack_h2(__float2half_rn(av[i].x),
                                       __float2half_rn(av[i].y)),
                               pack_h2(__float2half_rn(av[i].z),
                                       __float2half_rn(av[i].w)));
            }
#pragma unroll
            for (int i = 0; i < 4; i++) {
                int e = tid + (i + 4) * 512;
                int r = e >> 5, q = e & 31;
                av[i] = *(const float4*)(ts + (m0 + r) * 512 + (g + 1) * 128 +
                                         q * 4);
            }
        }

#pragma unroll
        for (int ks = 4; ks < 8; ks++) {
            uint32_t a0, a1, a2, a3, a4, a5, a6, a7;
            ldsm4(aBase + aOff + ks * 32, a0, a1, a2, a3);
            ldsm4(aBase + aOff + ks * 32 + 16 * A_ROWB, a4, a5, a6, a7);
#pragma unroll
            for (int tp = 0; tp < 2; tp++) {
                uint32_t b0, b1, b2, b3;
                ldsm4(bBase0 + bo + ks * 32 + tp * 16 * B_ROWB, b0, b1, b2, b3);
                mma16816(acc[0][2 * tp], a0, a1, a2, a3, b0, b1);
                mma16816(acc[0][2 * tp + 1], a0, a1, a2, a3, b2, b3);
                mma16816(acc[1][2 * tp], a4, a5, a6, a7, b0, b1);
                mma16816(acc[1][2 * tp + 1], a4, a5, a6, a7, b2, b3);
            }
        }

        if (aPre) {
#pragma unroll
            for (int i = 0; i < 4; i++) {
                int e = tid + (i + 4) * 512;
                int r = e >> 5, q = e & 31;
                *(uint2*)(smem + r * A_ROWB + (g + 1) * 256 + q * 8) =
                    make_uint2(pack_h2(__float2half_rn(av[i].x),
                                       __float2half_rn(av[i].y)),
                               pack_h2(__float2half_rn(av[i].z),
                                       __float2half_rn(av[i].w)));
            }
        }

        if ((g & 3) == 3) {
            const int h0 = (g >> 2) * 128;
#pragma unroll
            for (int tm = 0; tm < 2; tm++) {
#pragma unroll
                for (int rh = 0; rh < 2; rh++) {
                    float cov = covr[tm][rh];
                    float rs = 0.0f;
#pragma unroll
                    for (int tn = 0; tn < 4; tn++) {
                        int h = h0 + wn * 32 + tn * 8 + (lane & 3) * 2;
                        float p0 = acc[tm][tn][rh * 2 + 0] + s_base[h] +
                                   cov * s_wcov[h];
                        float p1 = acc[tm][tn][rh * 2 + 1] + s_base[h + 1] +
                                   cov * s_wcov[h + 1];
                        rs += fast_tanh(p0) * s_w2[h] +
                              fast_tanh(p1) * s_w2[h + 1];
                    }
                    rsum[tm][rh] += rs;
#pragma unroll
                    for (int tn = 0; tn < 4; tn++) {
                        acc[tm][tn][rh * 2 + 0] = 0.0f;
                        acc[tm][tn][rh * 2 + 1] = 0.0f;
                    }
                }
            }
        }

        if (g < NST - 1) CP_WAIT0();
        __syncthreads();
    }

#pragma unroll
    for (int tm = 0; tm < 2; tm++) {
#pragma unroll
        for (int rh = 0; rh < 2; rh++) {
            float rs = rsum[tm][rh];
            rs += __shfl_xor_sync(0xffffffffu, rs, 1);
            rs += __shfl_xor_sync(0xffffffffu, rs, 2);
            int m_local = wm * 32 + tm * 16 + rh * 8 + (lane >> 2);
            if ((lane & 3) == 0) s_red[m_local * 4 + wn] = rs;
        }
    }
    __syncthreads();
    if (tid < 128)
        g_logits[m0 + tid] = (s_red[tid * 4] + s_red[tid * 4 + 1]) +
                             (s_red[tid * 4 + 2] + s_red[tid * 4 + 3]);
}

// ---------------------------------------------------------------------------
// K3: per-batch masked softmax (512 threads)
// ---------------------------------------------------------------------------
__global__ __launch_bounds__(512) void softmax_kernel(const int* __restrict__ tlen,
                                                      float* __restrict__ att_out) {
    int b = blockIdx.x;
    int tid = threadIdx.x;
    __shared__ float sl[NL];
    __shared__ float rbuf[512];
    int len = tlen[b];

    for (int l = tid; l < len; l += 512) sl[l] = g_logits[b * NL + l];
    __syncthreads();

    float mx = -INFINITY;
    for (int l = tid; l < len; l += 512) mx = fmaxf(mx, sl[l]);
    rbuf[tid] = mx;
    __syncthreads();
    for (int s = 256; s > 0; s >>= 1) {
        if (tid < s) rbuf[tid] = fmaxf(rbuf[tid], rbuf[tid + s]);
        __syncthreads();
    }
    mx = rbuf[0];
    __syncthreads();

    float sum = 0.0f;
    for (int l = tid; l < len; l += 512) {
        float e = fast_exp(sl[l] - mx);
        sl[l] = e;
        sum += e;
    }
    rbuf[tid] = sum;
    __syncthreads();
    for (int s = 256; s > 0; s >>= 1) {
        if (tid < s) rbuf[tid] = rbuf[tid] + rbuf[tid + s];
        __syncthreads();
    }
    float inv = 1.0f / rbuf[0];

    for (int l = tid; l < NL; l += 512)
        att_out[b * NL + l] = (l < len) ? sl[l] * inv : 0.0f;
}

// ---------------------------------------------------------------------------
// K4: context partials (work-compacted, MLP-optimized).
// 512 threads: thread owns column f=tid; 4 independent accumulators over l,
// unroll 8 -> 32 independent 128B-line loads in flight per warp group.
// ---------------------------------------------------------------------------
__global__ __launch_bounds__(512) void ctx_part_kernel(
    const float* __restrict__ ts, const float* __restrict__ att) {
    if ((int)blockIdx.x >= g_nwork) return;
    int wk = g_work[blockIdx.x];
    int b = wk >> 5;
    int c = wk & 31;
    int tid = threadIdx.x;

    __shared__ float sa[128];
    if (tid < 128) sa[tid] = att[b * NL + c * 128 + tid];
    __syncthreads();

    const float* base = ts + ((size_t)b * NL + c * 128) * 512 + tid;
    float a0 = 0.f, a1 = 0.f, a2 = 0.f, a3 = 0.f;
#pragma unroll 8
    for (int l = 0; l < 128; l += 4) {
        a0 += sa[l + 0] * base[(size_t)(l + 0) * 512];
        a1 += sa[l + 1] * base[(size_t)(l + 1) * 512];
        a2 += sa[l + 2] * base[(size_t)(l + 2) * 512];
        a3 += sa[l + 3] * base[(size_t)(l + 3) * 512];
    }
    g_ctx_part[((size_t)c * NB + b) * 512 + tid] = (a0 + a1) + (a2 + a3);
}

__global__ __launch_bounds__(512) void ctx_reduce_kernel(
    const int* __restrict__ tlen, float* __restrict__ ctx) {
    int b = blockIdx.x;
    int f = threadIdx.x;
    int nt = (tlen[b] + 127) >> 7;
    float s = 0.0f;
    for (int c = 0; c < nt; c++)
        s += g_ctx_part[((size_t)c * NB + b) * 512 + f];
    ctx[b * 512 + f] = s;
}

// ---------------------------------------------------------------------------
// Launch
// ---------------------------------------------------------------------------
extern "C" void kernel_launch(void* const* d_in, const int* in_sizes, int n_in,
                              void* d_out, int out_size) {
    const float* ts  = (const float*)d_in[0];
    const float* ss  = (const float*)d_in[1];
    const float* cov = (const float*)d_in[2];
    const float* W1  = (const float*)d_in[3];
    const float* b1  = (const float*)d_in[4];
    const float* W2  = (const float*)d_in[5];
    const int*   tl  = (const int*)d_in[7];
    float* out = (float*)d_out;
    float* ctx_out = out;             // [32,512]
    float* att_out = out + NB * 512;  // [32,4096]

    cudaFuncSetAttribute(gemm_kernel,
                         cudaFuncAttributeMaxDynamicSharedMemorySize, SMEM_TOTAL);

    prep_kernel<<<545, 512>>>(W1, ss, b1, tl);
    gemm_kernel<<<1024, 512, SMEM_TOTAL>>>(ts, W1, W2, cov);
    softmax_kernel<<<NB, 512>>>(tl, att_out);
    ctx_part_kernel<<<1024, 512>>>(ts, att_out);
    ctx_reduce_kernel<<<NB, 512>>>(tl, ctx_out);
}

// round 14
// speedup vs baseline: 1.1095x; 1.0411x over previous
#include <cuda_runtime.h>
#include <cuda_fp16.h>
#include <math.h>
#include <stdint.h>

// ---------------------------------------------------------------------------
// Problem constants
// ---------------------------------------------------------------------------
#define NB   32
#define NL   4096
#define NH   512
#define NC   1025
#define MTOT (NB * NL)   // 131072

#define MT   128         // m rows per CTA
#define NST  16          // 4 h-tiles x 4 k-stages of 128

// SMEM layout
#define A_ROWB 1040                    // 512 fp16 + 16B pad
#define SM_A   0
#define A_BYTES (128 * A_ROWB)         // 133120
#define B_ROWB 272                     // 128 fp16 + 16B pad
#define B_TILE (128 * B_ROWB)          // 34816
#define SM_B   A_BYTES
#define SM_TAB (A_BYTES + 2 * B_TILE)  // 202752
// tables: w2[512] base[512] wcov[512] red[512]
#define SMEM_TOTAL (SM_TAB + 8192)     // 210944

// ---------------------------------------------------------------------------
// Device scratch (static; no runtime allocation)
// ---------------------------------------------------------------------------
__device__ float g_base[NB * NH];
__device__ float g_logits[MTOT];
__device__ __half g_Bf[NH * 512];             // W1[:,0:512] fp16
__device__ float g_ctx_part[32 * NB * 512];
__device__ int g_work[1024];                  // compacted (b<<5)|tile list
__device__ int g_nwork;

// ---------------------------------------------------------------------------
// helpers
// ---------------------------------------------------------------------------
__device__ __forceinline__ uint32_t smem_u32(const void* p) {
    uint32_t a;
    asm("{ .reg .u64 t; cvta.to.shared.u64 t, %1; cvt.u32.u64 %0, t; }"
        : "=r"(a) : "l"(p));
    return a;
}

__device__ __forceinline__ void ldsm4(uint32_t addr, uint32_t& r0, uint32_t& r1,
                                      uint32_t& r2, uint32_t& r3) {
    asm volatile("ldmatrix.sync.aligned.m8n8.x4.shared.b16 {%0,%1,%2,%3}, [%4];"
                 : "=r"(r0), "=r"(r1), "=r"(r2), "=r"(r3) : "r"(addr));
}

__device__ __forceinline__ void mma16816(float* d, uint32_t a0, uint32_t a1,
                                         uint32_t a2, uint32_t a3, uint32_t b0,
                                         uint32_t b1) {
    asm volatile(
        "mma.sync.aligned.m16n8k16.row.col.f32.f16.f16.f32 "
        "{%0,%1,%2,%3}, {%4,%5,%6,%7}, {%8,%9}, {%0,%1,%2,%3};"
        : "+f"(d[0]), "+f"(d[1]), "+f"(d[2]), "+f"(d[3])
        : "r"(a0), "r"(a1), "r"(a2), "r"(a3), "r"(b0), "r"(b1));
}

__device__ __forceinline__ void cpasync16(uint32_t dst, const void* src) {
    asm volatile("cp.async.cg.shared.global [%0], [%1], 16;"
                 :: "r"(dst), "l"(src) : "memory");
}
#define CP_COMMIT() asm volatile("cp.async.commit_group;" ::: "memory")
#define CP_WAIT0()  asm volatile("cp.async.wait_group 0;" ::: "memory")

__device__ __forceinline__ float fast_tanh(float x) {
    float t = x * 2.885390081777927f;  // 2*log2(e)
    float e;
    asm("ex2.approx.f32 %0, %1;" : "=f"(e) : "f"(t));
    float r;
    asm("rcp.approx.f32 %0, %1;" : "=f"(r) : "f"(e + 1.0f));
    return 1.0f - 2.0f * r;
}
__device__ __forceinline__ float fast_exp(float x) {
    float t = x * 1.4426950408889634f;
    float e;
    asm("ex2.approx.f32 %0, %1;" : "=f"(e) : "f"(t));
    return e;
}
__device__ __forceinline__ uint32_t pack_h2(__half a, __half b) {
    __half2 v = __halves2half2(a, b);
    return *reinterpret_cast<uint32_t*>(&v);
}

// ---------------------------------------------------------------------------
// K0: fused prep. Blocks 0..511: convB row. Blocks 512..543: base[b,:].
// Block 544: worklist.
// ---------------------------------------------------------------------------
__global__ __launch_bounds__(512) void prep_kernel(
    const float* __restrict__ W1, const float* __restrict__ summary,
    const float* __restrict__ b1, const int* __restrict__ tlen) {
    int blk = blockIdx.x;
    int tid = threadIdx.x;

    if (blk < 512) {
        g_Bf[blk * 512 + tid] = __float2half_rn(W1[(size_t)blk * NC + tid]);
    } else if (blk < 544) {
        int b = blk - 512;
        __shared__ float ss[512];
        ss[tid] = summary[b * 512 + tid];
        __syncthreads();
        const float* w = W1 + (size_t)tid * NC + 512;
        float acc = b1[tid];
#pragma unroll 8
        for (int c = 0; c < 512; c++) acc += ss[c] * w[c];
        g_base[b * NH + tid] = acc;
    } else if (tid < 32) {
        int nt = (tlen[tid] + 127) >> 7;
        int off = nt;
#pragma unroll
        for (int d = 1; d < 32; d <<= 1) {
            int v = __shfl_up_sync(0xffffffffu, off, d);
            if (tid >= d) off += v;
        }
        int excl = off - nt;
        for (int t = 0; t < nt; t++) g_work[excl + t] = (tid << 5) | t;
        if (tid == 31) g_nwork = off;
    }
}

// ---------------------------------------------------------------------------
// K1: HMMA GEMM. 512 threads, 16 warps 4m x 4n. A resident (converted in a
// pipeline through the first h-tile), flat 16-stage B pipeline, register-
// accumulated logit partials (single smem reduction at the end).
// ---------------------------------------------------------------------------
__global__ __launch_bounds__(512, 1) void gemm_kernel(
    const float* __restrict__ ts, const float* __restrict__ W1,
    const float* __restrict__ W2, const float* __restrict__ coverage) {
    extern __shared__ char smem[];
    const uint32_t sb = smem_u32(smem);
    const int tid = threadIdx.x;
    const int lane = tid & 31;
    const int warp = tid >> 5;
    const int wm = warp & 3;   // m quadrant (32 rows)
    const int wn = warp >> 2;  // n quadrant (32 cols)

    if ((int)blockIdx.x >= g_nwork) return;
    const int wk = g_work[blockIdx.x];
    const int b = wk >> 5;
    const size_t m0 = (size_t)wk * MT;

    float* s_w2 = (float*)(smem + SM_TAB);            // 512
    float* s_base = (float*)(smem + SM_TAB + 2048);   // 512
    float* s_wcov = (float*)(smem + SM_TAB + 4096);   // 512
    float* s_red = (float*)(smem + SM_TAB + 6144);    // 128 x 4

    // ---- prologue: B stage 0 (async) + A chunk 0 conversion + tables ----
    {
#pragma unroll
        for (int i = 0; i < 4; i++) {
            int e = tid + i * 512;
            int r = e >> 4, c = e & 15;
            cpasync16(sb + SM_B + (uint32_t)(r * B_ROWB + c * 16),
                      g_Bf + (size_t)r * 512 + c * 8);
        }
        CP_COMMIT();

#pragma unroll
        for (int i = 0; i < 8; i++) {
            int e = tid + i * 512;
            int r = e >> 5, q = e & 31;
            float4 v = *(const float4*)(ts + (m0 + r) * 512 + q * 4);
            *(uint2*)(smem + r * A_ROWB + q * 8) = make_uint2(
                pack_h2(__float2half_rn(v.x), __float2half_rn(v.y)),
                pack_h2(__float2half_rn(v.z), __float2half_rn(v.w)));
        }

        s_w2[tid] = W2[tid];
        s_base[tid] = g_base[b * NH + tid];
        s_wcov[tid] = W1[(size_t)tid * NC + 1024];
        CP_WAIT0();
        __syncthreads();
    }

    const uint32_t aBase =
        sb + (uint32_t)((wm * 32 + (lane & 15)) * A_ROWB + (lane >> 4) * 16);
    const uint32_t bBase0 =
        sb + SM_B +
        (uint32_t)((wn * 32 + (lane & 7) + ((lane >> 4) & 1) * 8) * B_ROWB +
                   ((lane >> 3) & 1) * 16);

    float acc[2][4][4];
#pragma unroll
    for (int i = 0; i < 2; i++)
#pragma unroll
        for (int j = 0; j < 4; j++)
#pragma unroll
            for (int c = 0; c < 4; c++) acc[i][j][c] = 0.0f;

    float rsum[2][2] = {{0.0f, 0.0f}, {0.0f, 0.0f}};
    float covr[2][2];
#pragma unroll
    for (int tm = 0; tm < 2; tm++)
#pragma unroll
        for (int rh = 0; rh < 2; rh++)
            covr[tm][rh] =
                coverage[m0 + wm * 32 + tm * 16 + rh * 8 + (lane >> 2)];

    const int cr = tid >> 4;   // B cp.async row base (0..31), +32 per i
    const int ccB = tid & 15;  // 16B chunk in B row

    for (int g = 0; g < NST; g++) {
        const uint32_t bo = (uint32_t)((g & 1) * B_TILE);

        if (g < NST - 1) {
            const int gn = g + 1;
            const int htn = gn >> 2, sn = gn & 3;
            const uint32_t nbo = (uint32_t)((gn & 1) * B_TILE);
#pragma unroll
            for (int i = 0; i < 4; i++) {
                int r = cr + i * 32;
                cpasync16(sb + SM_B + nbo + (uint32_t)(r * B_ROWB + ccB * 16),
                          g_Bf + (size_t)(htn * 128 + r) * 512 + sn * 128 +
                              ccB * 8);
            }
            CP_COMMIT();
        }

        const bool aPre = (g < 3);
        float4 av[4];
        if (aPre) {
#pragma unroll
            for (int i = 0; i < 4; i++) {
                int e = tid + i * 512;
                int r = e >> 5, q = e & 31;
                av[i] = *(const float4*)(ts + (m0 + r) * 512 + (g + 1) * 128 +
                                         q * 4);
            }
        }

        const uint32_t aOff = (uint32_t)((g & 3) * 256);
#pragma unroll
        for (int ks = 0; ks < 4; ks++) {
            uint32_t a0, a1, a2, a3, a4, a5, a6, a7;
            ldsm4(aBase + aOff + ks * 32, a0, a1, a2, a3);
            ldsm4(aBase + aOff + ks * 32 + 16 * A_ROWB, a4, a5, a6, a7);
#pragma unroll
            for (int tp = 0; tp < 2; tp++) {
                uint32_t b0, b1, b2, b3;
                ldsm4(bBase0 + bo + ks * 32 + tp * 16 * B_ROWB, b0, b1, b2, b3);
                mma16816(acc[0][2 * tp], a0, a1, a2, a3, b0, b1);
                mma16816(acc[0][2 * tp + 1], a0, a1, a2, a3, b2, b3);
                mma16816(acc[1][2 * tp], a4, a5, a6, a7, b0, b1);
                mma16816(acc[1][2 * tp + 1], a4, a5, a6, a7, b2, b3);
            }
        }

        if (aPre) {
#pragma unroll
            for (int i = 0; i < 4; i++) {
                int e = tid + i * 512;
                int r = e >> 5, q = e & 31;
                *(uint2*)(smem + r * A_ROWB + (g + 1) * 256 + q * 8) =
                    make_uint2(pack_h2(__float2half_rn(av[i].x),
                                       __float2half_rn(av[i].y)),
                               pack_h2(__float2half_rn(av[i].z),
                                       __float2half_rn(av[i].w)));
            }
#pragma unroll
            for (int i = 0; i < 4; i++) {
                int e = tid + (i + 4) * 512;
                int r = e >> 5, q = e & 31;
                av[i] = *(const float4*)(ts + (m0 + r) * 512 + (g + 1) * 128 +
                                         q * 4);
            }
        }

#pragma unroll
        for (int ks = 4; ks < 8; ks++) {
            uint32_t a0, a1, a2, a3, a4, a5, a6, a7;
            ldsm4(aBase + aOff + ks * 32, a0, a1, a2, a3);
            ldsm4(aBase + aOff + ks * 32 + 16 * A_ROWB, a4, a5, a6, a7);
#pragma unroll
            for (int tp = 0; tp < 2; tp++) {
                uint32_t b0, b1, b2, b3;
                ldsm4(bBase0 + bo + ks * 32 + tp * 16 * B_ROWB, b0, b1, b2, b3);
                mma16816(acc[0][2 * tp], a0, a1, a2, a3, b0, b1);
                mma16816(acc[0][2 * tp + 1], a0, a1, a2, a3, b2, b3);
                mma16816(acc[1][2 * tp], a4, a5, a6, a7, b0, b1);
                mma16816(acc[1][2 * tp + 1], a4, a5, a6, a7, b2, b3);
            }
        }

        if (aPre) {
#pragma unroll
            for (int i = 0; i < 4; i++) {
                int e = tid + (i + 4) * 512;
                int r = e >> 5, q = e & 31;
                *(uint2*)(smem + r * A_ROWB + (g + 1) * 256 + q * 8) =
                    make_uint2(pack_h2(__float2half_rn(av[i].x),
                                       __float2half_rn(av[i].y)),
                               pack_h2(__float2half_rn(av[i].z),
                                       __float2half_rn(av[i].w)));
            }
        }

        if ((g & 3) == 3) {
            const int h0 = (g >> 2) * 128;
#pragma unroll
            for (int tm = 0; tm < 2; tm++) {
#pragma unroll
                for (int rh = 0; rh < 2; rh++) {
                    float cov = covr[tm][rh];
                    float rs = 0.0f;
#pragma unroll
                    for (int tn = 0; tn < 4; tn++) {
                        int h = h0 + wn * 32 + tn * 8 + (lane & 3) * 2;
                        float p0 = acc[tm][tn][rh * 2 + 0] + s_base[h] +
                                   cov * s_wcov[h];
                        float p1 = acc[tm][tn][rh * 2 + 1] + s_base[h + 1] +
                                   cov * s_wcov[h + 1];
                        rs += fast_tanh(p0) * s_w2[h] +
                              fast_tanh(p1) * s_w2[h + 1];
                    }
                    rsum[tm][rh] += rs;
#pragma unroll
                    for (int tn = 0; tn < 4; tn++) {
                        acc[tm][tn][rh * 2 + 0] = 0.0f;
                        acc[tm][tn][rh * 2 + 1] = 0.0f;
                    }
                }
            }
        }

        if (g < NST - 1) CP_WAIT0();
        __syncthreads();
    }

#pragma unroll
    for (int tm = 0; tm < 2; tm++) {
#pragma unroll
        for (int rh = 0; rh < 2; rh++) {
            float rs = rsum[tm][rh];
            rs += __shfl_xor_sync(0xffffffffu, rs, 1);
            rs += __shfl_xor_sync(0xffffffffu, rs, 2);
            int m_local = wm * 32 + tm * 16 + rh * 8 + (lane >> 2);
            if ((lane & 3) == 0) s_red[m_local * 4 + wn] = rs;
        }
    }
    __syncthreads();
    if (tid < 128)
        g_logits[m0 + tid] = (s_red[tid * 4] + s_red[tid * 4 + 1]) +
                             (s_red[tid * 4 + 2] + s_red[tid * 4 + 3]);
}

// ---------------------------------------------------------------------------
// K3: per-batch masked softmax (512 threads)
// ---------------------------------------------------------------------------
__global__ __launch_bounds__(512) void softmax_kernel(const int* __restrict__ tlen,
                                                      float* __restrict__ att_out) {
    int b = blockIdx.x;
    int tid = threadIdx.x;
    __shared__ float sl[NL];
    __shared__ float rbuf[512];
    int len = tlen[b];

    for (int l = tid; l < len; l += 512) sl[l] = g_logits[b * NL + l];
    __syncthreads();

    float mx = -INFINITY;
    for (int l = tid; l < len; l += 512) mx = fmaxf(mx, sl[l]);
    rbuf[tid] = mx;
    __syncthreads();
    for (int s = 256; s > 0; s >>= 1) {
        if (tid < s) rbuf[tid] = fmaxf(rbuf[tid], rbuf[tid + s]);
        __syncthreads();
    }
    mx = rbuf[0];
    __syncthreads();

    float sum = 0.0f;
    for (int l = tid; l < len; l += 512) {
        float e = fast_exp(sl[l] - mx);
        sl[l] = e;
        sum += e;
    }
    rbuf[tid] = sum;
    __syncthreads();
    for (int s = 256; s > 0; s >>= 1) {
        if (tid < s) rbuf[tid] = rbuf[tid] + rbuf[tid + s];
        __syncthreads();
    }
    float inv = 1.0f / rbuf[0];

    for (int l = tid; l < NL; l += 512)
        att_out[b * NL + l] = (l < len) ? sl[l] * inv : 0.0f;
}

// ---------------------------------------------------------------------------
// K4: context partials (work-compacted, float4 across f for 16B loads).
// 512 threads: fq = tid&127 (float4 column group), lg = tid>>7 (32-row
// l-subgroup). 32 independent 16B loads per thread; 4-way smem reduction.
// ---------------------------------------------------------------------------
__global__ __launch_bounds__(512) void ctx_part_kernel(
    const float* __restrict__ ts, const float* __restrict__ att) {
    if ((int)blockIdx.x >= g_nwork) return;
    int wk = g_work[blockIdx.x];
    int b = wk >> 5;
    int c = wk & 31;
    int tid = threadIdx.x;
    const int fq = tid & 127;
    const int lg = tid >> 7;

    __shared__ float sa[128];
    __shared__ float4 red[512];
    if (tid < 128) sa[tid] = att[b * NL + c * 128 + tid];
    __syncthreads();

    const float4* base =
        (const float4*)(ts + ((size_t)b * NL + c * 128) * 512) + fq;
    float4 acc = make_float4(0.f, 0.f, 0.f, 0.f);
#pragma unroll 8
    for (int i = 0; i < 32; i++) {
        int l = lg * 32 + i;
        float w = sa[l];
        float4 v = base[(size_t)l * 128];
        acc.x += w * v.x;
        acc.y += w * v.y;
        acc.z += w * v.z;
        acc.w += w * v.w;
    }
    red[tid] = acc;
    __syncthreads();

    if (tid < 128) {
        float4 r0 = red[tid], r1 = red[tid + 128];
        float4 r2 = red[tid + 256], r3 = red[tid + 384];
        float4 s;
        s.x = (r0.x + r1.x) + (r2.x + r3.x);
        s.y = (r0.y + r1.y) + (r2.y + r3.y);
        s.z = (r0.z + r1.z) + (r2.z + r3.z);
        s.w = (r0.w + r1.w) + (r2.w + r3.w);
        *((float4*)(g_ctx_part + ((size_t)c * NB + b) * 512) + tid) = s;
    }
}

__global__ __launch_bounds__(512) void ctx_reduce_kernel(
    const int* __restrict__ tlen, float* __restrict__ ctx) {
    int b = blockIdx.x;
    int f = threadIdx.x;
    int nt = (tlen[b] + 127) >> 7;
    float s = 0.0f;
    for (int c = 0; c < nt; c++)
        s += g_ctx_part[((size_t)c * NB + b) * 512 + f];
    ctx[b * 512 + f] = s;
}

// ---------------------------------------------------------------------------
// Launch
// ---------------------------------------------------------------------------
extern "C" void kernel_launch(void* const* d_in, const int* in_sizes, int n_in,
                              void* d_out, int out_size) {
    const float* ts  = (const float*)d_in[0];
    const float* ss  = (const float*)d_in[1];
    const float* cov = (const float*)d_in[2];
    const float* W1  = (const float*)d_in[3];
    const float* b1  = (const float*)d_in[4];
    const float* W2  = (const float*)d_in[5];
    const int*   tl  = (const int*)d_in[7];
    float* out = (float*)d_out;
    float* ctx_out = out;             // [32,512]
    float* att_out = out + NB * 512;  // [32,4096]

    cudaFuncSetAttribute(gemm_kernel,
                         cudaFuncAttributeMaxDynamicSharedMemorySize, SMEM_TOTAL);

    prep_kernel<<<545, 512>>>(W1, ss, b1, tl);
    gemm_kernel<<<1024, 512, SMEM_TOTAL>>>(ts, W1, W2, cov);
    softmax_kernel<<<NB, 512>>>(tl, att_out);
    ctx_part_kernel<<<1024, 512>>>(ts, att_out);
    ctx_reduce_kernel<<<NB, 512>>>(tl, ctx_out);
}

// round 15
// speedup vs baseline: 1.1156x; 1.0054x over previous
#include <cuda_runtime.h>
#include <cuda_fp16.h>
#include <math.h>
#include <stdint.h>

// ---------------------------------------------------------------------------
// Problem constants
// ---------------------------------------------------------------------------
#define NB   32
#define NL   4096
#define NH   512
#define NC   1025
#define MTOT (NB * NL)   // 131072

#define MT   128         // m rows per CTA
#define NST  16          // 4 h-tiles x 4 k-stages of 128

// SMEM layout
#define A_ROWB 1040                    // 512 fp16 + 16B pad
#define SM_A   0
#define A_BYTES (128 * A_ROWB)         // 133120
#define B_ROWB 272                     // 128 fp16 + 16B pad
#define B_TILE (128 * B_ROWB)          // 34816
#define SM_B   A_BYTES
#define SM_TAB (A_BYTES + 2 * B_TILE)  // 202752
// tables: w2[512] base[512] wcov[512] red[512]
#define SMEM_TOTAL (SM_TAB + 8192)     // 210944

// ---------------------------------------------------------------------------
// Device scratch (static; no runtime allocation)
// ---------------------------------------------------------------------------
__device__ float g_base[NB * NH];
__device__ float g_logits[MTOT];
__device__ __half g_Bf[NH * 512];             // W1[:,0:512] fp16
__device__ float g_ctx_part[32 * NB * 512];
__device__ int g_work[1024];                  // compacted (b<<5)|tile list
__device__ int g_nwork;

// ---------------------------------------------------------------------------
// helpers
// ---------------------------------------------------------------------------
__device__ __forceinline__ uint32_t smem_u32(const void* p) {
    uint32_t a;
    asm("{ .reg .u64 t; cvta.to.shared.u64 t, %1; cvt.u32.u64 %0, t; }"
        : "=r"(a) : "l"(p));
    return a;
}

__device__ __forceinline__ void ldsm4(uint32_t addr, uint32_t& r0, uint32_t& r1,
                                      uint32_t& r2, uint32_t& r3) {
    asm volatile("ldmatrix.sync.aligned.m8n8.x4.shared.b16 {%0,%1,%2,%3}, [%4];"
                 : "=r"(r0), "=r"(r1), "=r"(r2), "=r"(r3) : "r"(addr));
}

__device__ __forceinline__ void mma16816(float* d, uint32_t a0, uint32_t a1,
                                         uint32_t a2, uint32_t a3, uint32_t b0,
                                         uint32_t b1) {
    asm volatile(
        "mma.sync.aligned.m16n8k16.row.col.f32.f16.f16.f32 "
        "{%0,%1,%2,%3}, {%4,%5,%6,%7}, {%8,%9}, {%0,%1,%2,%3};"
        : "+f"(d[0]), "+f"(d[1]), "+f"(d[2]), "+f"(d[3])
        : "r"(a0), "r"(a1), "r"(a2), "r"(a3), "r"(b0), "r"(b1));
}

__device__ __forceinline__ void cpasync16(uint32_t dst, const void* src) {
    asm volatile("cp.async.cg.shared.global [%0], [%1], 16;"
                 :: "r"(dst), "l"(src) : "memory");
}
#define CP_COMMIT() asm volatile("cp.async.commit_group;" ::: "memory")
#define CP_WAIT0()  asm volatile("cp.async.wait_group 0;" ::: "memory")

__device__ __forceinline__ float fast_tanh(float x) {
    float t = x * 2.885390081777927f;  // 2*log2(e)
    float e;
    asm("ex2.approx.f32 %0, %1;" : "=f"(e) : "f"(t));
    float r;
    asm("rcp.approx.f32 %0, %1;" : "=f"(r) : "f"(e + 1.0f));
    return 1.0f - 2.0f * r;
}
__device__ __forceinline__ float fast_exp(float x) {
    float t = x * 1.4426950408889634f;
    float e;
    asm("ex2.approx.f32 %0, %1;" : "=f"(e) : "f"(t));
    return e;
}
__device__ __forceinline__ uint32_t pack_h2(__half a, __half b) {
    __half2 v = __halves2half2(a, b);
    return *reinterpret_cast<uint32_t*>(&v);
}

// ---------------------------------------------------------------------------
// K0: fused prep. Blocks 0..511: convB row. Blocks 512..543: base[b,:].
// Block 544: worklist.
// ---------------------------------------------------------------------------
__global__ __launch_bounds__(512) void prep_kernel(
    const float* __restrict__ W1, const float* __restrict__ summary,
    const float* __restrict__ b1, const int* __restrict__ tlen) {
    int blk = blockIdx.x;
    int tid = threadIdx.x;

    if (blk < 512) {
        g_Bf[blk * 512 + tid] = __float2half_rn(W1[(size_t)blk * NC + tid]);
    } else if (blk < 544) {
        int b = blk - 512;
        __shared__ float ss[512];
        ss[tid] = summary[b * 512 + tid];
        __syncthreads();
        const float* w = W1 + (size_t)tid * NC + 512;
        float acc = b1[tid];
#pragma unroll 8
        for (int c = 0; c < 512; c++) acc += ss[c] * w[c];
        g_base[b * NH + tid] = acc;
    } else if (tid < 32) {
        int nt = (tlen[tid] + 127) >> 7;
        int off = nt;
#pragma unroll
        for (int d = 1; d < 32; d <<= 1) {
            int v = __shfl_up_sync(0xffffffffu, off, d);
            if (tid >= d) off += v;
        }
        int excl = off - nt;
        for (int t = 0; t < nt; t++) g_work[excl + t] = (tid << 5) | t;
        if (tid == 31) g_nwork = off;
    }
}

// ---------------------------------------------------------------------------
// K1: HMMA GEMM. 512 threads, 16 warps 4m x 4n. A resident (converted in a
// pipeline through the first h-tile), flat 16-stage B pipeline, register-
// accumulated logit partials (single smem reduction at the end).
// ---------------------------------------------------------------------------
__global__ __launch_bounds__(512, 1) void gemm_kernel(
    const float* __restrict__ ts, const float* __restrict__ W1,
    const float* __restrict__ W2, const float* __restrict__ coverage) {
    extern __shared__ char smem[];
    const uint32_t sb = smem_u32(smem);
    const int tid = threadIdx.x;
    const int lane = tid & 31;
    const int warp = tid >> 5;
    const int wm = warp & 3;   // m quadrant (32 rows)
    const int wn = warp >> 2;  // n quadrant (32 cols)

    if ((int)blockIdx.x >= g_nwork) return;
    const int wk = g_work[blockIdx.x];
    const int b = wk >> 5;
    const size_t m0 = (size_t)wk * MT;

    float* s_w2 = (float*)(smem + SM_TAB);            // 512
    float* s_base = (float*)(smem + SM_TAB + 2048);   // 512
    float* s_wcov = (float*)(smem + SM_TAB + 4096);   // 512
    float* s_red = (float*)(smem + SM_TAB + 6144);    // 128 x 4

    // ---- prologue: B stage 0 (async) + A chunk 0 conversion + tables ----
    {
#pragma unroll
        for (int i = 0; i < 4; i++) {
            int e = tid + i * 512;
            int r = e >> 4, c = e & 15;
            cpasync16(sb + SM_B + (uint32_t)(r * B_ROWB + c * 16),
                      g_Bf + (size_t)r * 512 + c * 8);
        }
        CP_COMMIT();

#pragma unroll
        for (int i = 0; i < 8; i++) {
            int e = tid + i * 512;
            int r = e >> 5, q = e & 31;
            float4 v = *(const float4*)(ts + (m0 + r) * 512 + q * 4);
            *(uint2*)(smem + r * A_ROWB + q * 8) = make_uint2(
                pack_h2(__float2half_rn(v.x), __float2half_rn(v.y)),
                pack_h2(__float2half_rn(v.z), __float2half_rn(v.w)));
        }

        s_w2[tid] = W2[tid];
        s_base[tid] = g_base[b * NH + tid];
        s_wcov[tid] = W1[(size_t)tid * NC + 1024];
        CP_WAIT0();
        __syncthreads();
    }

    const uint32_t aBase =
        sb + (uint32_t)((wm * 32 + (lane & 15)) * A_ROWB + (lane >> 4) * 16);
    const uint32_t bBase0 =
        sb + SM_B +
        (uint32_t)((wn * 32 + (lane & 7) + ((lane >> 4) & 1) * 8) * B_ROWB +
                   ((lane >> 3) & 1) * 16);

    float acc[2][4][4];
#pragma unroll
    for (int i = 0; i < 2; i++)
#pragma unroll
        for (int j = 0; j < 4; j++)
#pragma unroll
            for (int c = 0; c < 4; c++) acc[i][j][c] = 0.0f;

    float rsum[2][2] = {{0.0f, 0.0f}, {0.0f, 0.0f}};
    float covr[2][2];
#pragma unroll
    for (int tm = 0; tm < 2; tm++)
#pragma unroll
        for (int rh = 0; rh < 2; rh++)
            covr[tm][rh] =
                coverage[m0 + wm * 32 + tm * 16 + rh * 8 + (lane >> 2)];

    const int cr = tid >> 4;   // B cp.async row base (0..31), +32 per i
    const int ccB = tid & 15;  // 16B chunk in B row

    for (int g = 0; g < NST; g++) {
        const uint32_t bo = (uint32_t)((g & 1) * B_TILE);

        if (g < NST - 1) {
            const int gn = g + 1;
            const int htn = gn >> 2, sn = gn & 3;
            const uint32_t nbo = (uint32_t)((gn & 1) * B_TILE);
#pragma unroll
            for (int i = 0; i < 4; i++) {
                int r = cr + i * 32;
                cpasync16(sb + SM_B + nbo + (uint32_t)(r * B_ROWB + ccB * 16),
                          g_Bf + (size_t)(htn * 128 + r) * 512 + sn * 128 +
                              ccB * 8);
            }
            CP_COMMIT();
        }

        const bool aPre = (g < 3);
        float4 av[4];
        if (aPre) {
#pragma unroll
            for (int i = 0; i < 4; i++) {
                int e = tid + i * 512;
                int r = e >> 5, q = e & 31;
                av[i] = *(const float4*)(ts + (m0 + r) * 512 + (g + 1) * 128 +
                                         q * 4);
            }
        }

        const uint32_t aOff = (uint32_t)((g & 3) * 256);
#pragma unroll
        for (int ks = 0; ks < 4; ks++) {
            uint32_t a0, a1, a2, a3, a4, a5, a6, a7;
            ldsm4(aBase + aOff + ks * 32, a0, a1, a2, a3);
            ldsm4(aBase + aOff + ks * 32 + 16 * A_ROWB, a4, a5, a6, a7);
#pragma unroll
            for (int tp = 0; tp < 2; tp++) {
                uint32_t b0, b1, b2, b3;
                ldsm4(bBase0 + bo + ks * 32 + tp * 16 * B_ROWB, b0, b1, b2, b3);
                mma16816(acc[0][2 * tp], a0, a1, a2, a3, b0, b1);
                mma16816(acc[0][2 * tp + 1], a0, a1, a2, a3, b2, b3);
                mma16816(acc[1][2 * tp], a4, a5, a6, a7, b0, b1);
                mma16816(acc[1][2 * tp + 1], a4, a5, a6, a7, b2, b3);
            }
        }

        if (aPre) {
#pragma unroll
            for (int i = 0; i < 4; i++) {
                int e = tid + i * 512;
                int r = e >> 5, q = e & 31;
                *(uint2*)(smem + r * A_ROWB + (g + 1) * 256 + q * 8) =
                    make_uint2(pack_h2(__float2half_rn(av[i].x),
                                       __float2half_rn(av[i].y)),
                               pack_h2(__float2half_rn(av[i].z),
                                       __float2half_rn(av[i].w)));
            }
#pragma unroll
            for (int i = 0; i < 4; i++) {
                int e = tid + (i + 4) * 512;
                int r = e >> 5, q = e & 31;
                av[i] = *(const float4*)(ts + (m0 + r) * 512 + (g + 1) * 128 +
                                         q * 4);
            }
        }

#pragma unroll
        for (int ks = 4; ks < 8; ks++) {
            uint32_t a0, a1, a2, a3, a4, a5, a6, a7;
            ldsm4(aBase + aOff + ks * 32, a0, a1, a2, a3);
            ldsm4(aBase + aOff + ks * 32 + 16 * A_ROWB, a4, a5, a6, a7);
#pragma unroll
            for (int tp = 0; tp < 2; tp++) {
                uint32_t b0, b1, b2, b3;
                ldsm4(bBase0 + bo + ks * 32 + tp * 16 * B_ROWB, b0, b1, b2, b3);
                mma16816(acc[0][2 * tp], a0, a1, a2, a3, b0, b1);
                mma16816(acc[0][2 * tp + 1], a0, a1, a2, a3, b2, b3);
                mma16816(acc[1][2 * tp], a4, a5, a6, a7, b0, b1);
                mma16816(acc[1][2 * tp + 1], a4, a5, a6, a7, b2, b3);
            }
        }

        if (aPre) {
#pragma unroll
            for (int i = 0; i < 4; i++) {
                int e = tid + (i + 4) * 512;
                int r = e >> 5, q = e & 31;
                *(uint2*)(smem + r * A_ROWB + (g + 1) * 256 + q * 8) =
                    make_uint2(pack_h2(__float2half_rn(av[i].x),
                                       __float2half_rn(av[i].y)),
                               pack_h2(__float2half_rn(av[i].z),
                                       __float2half_rn(av[i].w)));
            }
        }

        if ((g & 3) == 3) {
            const int h0 = (g >> 2) * 128;
#pragma unroll
            for (int tm = 0; tm < 2; tm++) {
#pragma unroll
                for (int rh = 0; rh < 2; rh++) {
                    float cov = covr[tm][rh];
                    float rs = 0.0f;
#pragma unroll
                    for (int tn = 0; tn < 4; tn++) {
                        int h = h0 + wn * 32 + tn * 8 + (lane & 3) * 2;
                        float p0 = acc[tm][tn][rh * 2 + 0] + s_base[h] +
                                   cov * s_wcov[h];
                        float p1 = acc[tm][tn][rh * 2 + 1] + s_base[h + 1] +
                                   cov * s_wcov[h + 1];
                        rs += fast_tanh(p0) * s_w2[h] +
                              fast_tanh(p1) * s_w2[h + 1];
                    }
                    rsum[tm][rh] += rs;
#pragma unroll
                    for (int tn = 0; tn < 4; tn++) {
                        acc[tm][tn][rh * 2 + 0] = 0.0f;
                        acc[tm][tn][rh * 2 + 1] = 0.0f;
                    }
                }
            }
        }

        if (g < NST - 1) CP_WAIT0();
        __syncthreads();
    }

#pragma unroll
    for (int tm = 0; tm < 2; tm++) {
#pragma unroll
        for (int rh = 0; rh < 2; rh++) {
            float rs = rsum[tm][rh];
            rs += __shfl_xor_sync(0xffffffffu, rs, 1);
            rs += __shfl_xor_sync(0xffffffffu, rs, 2);
            int m_local = wm * 32 + tm * 16 + rh * 8 + (lane >> 2);
            if ((lane & 3) == 0) s_red[m_local * 4 + wn] = rs;
        }
    }
    __syncthreads();
    if (tid < 128)
        g_logits[m0 + tid] = (s_red[tid * 4] + s_red[tid * 4 + 1]) +
                             (s_red[tid * 4 + 2] + s_red[tid * 4 + 3]);
}

// ---------------------------------------------------------------------------
// K3: per-batch masked softmax (512 threads)
// ---------------------------------------------------------------------------
__global__ __launch_bounds__(512) void softmax_kernel(const int* __restrict__ tlen,
                                                      float* __restrict__ att_out) {
    int b = blockIdx.x;
    int tid = threadIdx.x;
    __shared__ float sl[NL];
    __shared__ float rbuf[512];
    int len = tlen[b];

    for (int l = tid; l < len; l += 512) sl[l] = g_logits[b * NL + l];
    __syncthreads();

    float mx = -INFINITY;
    for (int l = tid; l < len; l += 512) mx = fmaxf(mx, sl[l]);
    rbuf[tid] = mx;
    __syncthreads();
    for (int s = 256; s > 0; s >>= 1) {
        if (tid < s) rbuf[tid] = fmaxf(rbuf[tid], rbuf[tid + s]);
        __syncthreads();
    }
    mx = rbuf[0];
    __syncthreads();

    float sum = 0.0f;
    for (int l = tid; l < len; l += 512) {
        float e = fast_exp(sl[l] - mx);
        sl[l] = e;
        sum += e;
    }
    rbuf[tid] = sum;
    __syncthreads();
    for (int s = 256; s > 0; s >>= 1) {
        if (tid < s) rbuf[tid] = rbuf[tid] + rbuf[tid + s];
        __syncthreads();
    }
    float inv = 1.0f / rbuf[0];

    for (int l = tid; l < NL; l += 512)
        att_out[b * NL + l] = (l < len) ? sl[l] * inv : 0.0f;
}

// ---------------------------------------------------------------------------
// K4: context partials. float4 across f; explicit 8-deep load batches
// (128B in flight per thread) to force MLP.
// ---------------------------------------------------------------------------
__global__ __launch_bounds__(512) void ctx_part_kernel(
    const float* __restrict__ ts, const float* __restrict__ att) {
    if ((int)blockIdx.x >= g_nwork) return;
    int wk = g_work[blockIdx.x];
    int b = wk >> 5;
    int c = wk & 31;
    int tid = threadIdx.x;
    const int fq = tid & 127;
    const int lg = tid >> 7;

    __shared__ float sa[128];
    __shared__ float4 red[512];
    if (tid < 128) sa[tid] = att[b * NL + c * 128 + tid];
    __syncthreads();

    const float4* base =
        (const float4*)(ts + ((size_t)b * NL + c * 128) * 512) + fq;
    float4 acc = make_float4(0.f, 0.f, 0.f, 0.f);

#pragma unroll
    for (int bt = 0; bt < 4; bt++) {
        const int l0 = lg * 32 + bt * 8;
        // batch-load 8 independent float4 (128B in flight)
        float4 v[8];
#pragma unroll
        for (int j = 0; j < 8; j++) v[j] = base[(size_t)(l0 + j) * 128];
#pragma unroll
        for (int j = 0; j < 8; j++) {
            float w = sa[l0 + j];
            acc.x += w * v[j].x;
            acc.y += w * v[j].y;
            acc.z += w * v[j].z;
            acc.w += w * v[j].w;
        }
    }
    red[tid] = acc;
    __syncthreads();

    if (tid < 128) {
        float4 r0 = red[tid], r1 = red[tid + 128];
        float4 r2 = red[tid + 256], r3 = red[tid + 384];
        float4 s;
        s.x = (r0.x + r1.x) + (r2.x + r3.x);
        s.y = (r0.y + r1.y) + (r2.y + r3.y);
        s.z = (r0.z + r1.z) + (r2.z + r3.z);
        s.w = (r0.w + r1.w) + (r2.w + r3.w);
        *((float4*)(g_ctx_part + ((size_t)c * NB + b) * 512) + tid) = s;
    }
}

__global__ __launch_bounds__(512) void ctx_reduce_kernel(
    const int* __restrict__ tlen, float* __restrict__ ctx) {
    int b = blockIdx.x;
    int f = threadIdx.x;
    int nt = (tlen[b] + 127) >> 7;
    float s = 0.0f;
    for (int c = 0; c < nt; c++)
        s += g_ctx_part[((size_t)c * NB + b) * 512 + f];
    ctx[b * 512 + f] = s;
}

// ---------------------------------------------------------------------------
// Launch
// ---------------------------------------------------------------------------
extern "C" void kernel_launch(void* const* d_in, const int* in_sizes, int n_in,
                              void* d_out, int out_size) {
    const float* ts  = (const float*)d_in[0];
    const float* ss  = (const float*)d_in[1];
    const float* cov = (const float*)d_in[2];
    const float* W1  = (const float*)d_in[3];
    const float* b1  = (const float*)d_in[4];
    const float* W2  = (const float*)d_in[5];
    const int*   tl  = (const int*)d_in[7];
    float* out = (float*)d_out;
    float* ctx_out = out;             // [32,512]
    float* att_out = out + NB * 512;  // [32,4096]

    cudaFuncSetAttribute(gemm_kernel,
                         cudaFuncAttributeMaxDynamicSharedMemorySize, SMEM_TOTAL);

    prep_kernel<<<545, 512>>>(W1, ss, b1, tl);
    gemm_kernel<<<1024, 512, SMEM_TOTAL>>>(ts, W1, W2, cov);
    softmax_kernel<<<NB, 512>>>(tl, att_out);
    ctx_part_kernel<<<1024, 512>>>(ts, att_out);
    ctx_reduce_kernel<<<NB, 512>>>(tl, ctx_out);
}